// round 1
// baseline (speedup 1.0000x reference)
#include <cuda_runtime.h>
#include <math.h>

#define DIM   3072
#define HEADS 24
#define HD    128
#define BB    2
#define LL    2048
#define MTOT  (BB*LL)          // 4096 rows
#define NQKV  (3*DIM)          // 9216

// ---------------- scratch (static device globals; no runtime alloc) ----------------
__device__ float g_qkv[(size_t)MTOT * NQKV];        // [B*L, 3*DIM]  ~151 MB
__device__ float g_q  [(size_t)BB*HEADS*LL*HD];     // [B,H,L,D]     ~50 MB
__device__ float g_k  [(size_t)BB*HEADS*LL*HD];
__device__ float g_v  [(size_t)BB*HEADS*LL*HD];
__device__ float g_att[(size_t)MTOT * DIM];         // [B,L,DIM]     ~50 MB

// =====================================================================
// Kernel 1/4: C[M,N] = A[M,K] * W[N,K]^T + bias[N]   (fp32, 128x128x16)
// =====================================================================
__global__ __launch_bounds__(256) void gemm_nt_bias(
    const float* __restrict__ A, const float* __restrict__ W,
    const float* __restrict__ bias, float* __restrict__ C,
    int N, int K)
{
    __shared__ float As[16][132];   // [k][m], padded
    __shared__ float Bs[16][132];   // [k][n], padded
    const int tid = threadIdx.x;
    const int tx = tid & 15, ty = tid >> 4;
    const int bm = blockIdx.y * 128, bn = blockIdx.x * 128;
    const int lrow = tid >> 2;          // 0..63
    const int lcol = (tid & 3) << 2;    // 0,4,8,12

    float acc[8][8];
    #pragma unroll
    for (int i = 0; i < 8; ++i)
        #pragma unroll
        for (int j = 0; j < 8; ++j) acc[i][j] = 0.f;

    const float* Ag = A + (size_t)(bm + lrow) * K + lcol;
    const float* Wg = W + (size_t)(bn + lrow) * K + lcol;

    for (int k0 = 0; k0 < K; k0 += 16) {
        #pragma unroll
        for (int hh = 0; hh < 2; ++hh) {
            float4 va = *(const float4*)(Ag + (size_t)hh * 64 * K + k0);
            int r = lrow + hh * 64;
            As[lcol+0][r] = va.x; As[lcol+1][r] = va.y;
            As[lcol+2][r] = va.z; As[lcol+3][r] = va.w;
            float4 vb = *(const float4*)(Wg + (size_t)hh * 64 * K + k0);
            Bs[lcol+0][r] = vb.x; Bs[lcol+1][r] = vb.y;
            Bs[lcol+2][r] = vb.z; Bs[lcol+3][r] = vb.w;
        }
        __syncthreads();
        #pragma unroll
        for (int kk = 0; kk < 16; ++kk) {
            float4 a0 = *(const float4*)&As[kk][ty*8];
            float4 a1 = *(const float4*)&As[kk][ty*8+4];
            float4 b0 = *(const float4*)&Bs[kk][tx*8];
            float4 b1 = *(const float4*)&Bs[kk][tx*8+4];
            float a[8] = {a0.x,a0.y,a0.z,a0.w,a1.x,a1.y,a1.z,a1.w};
            float b[8] = {b0.x,b0.y,b0.z,b0.w,b1.x,b1.y,b1.z,b1.w};
            #pragma unroll
            for (int i = 0; i < 8; ++i)
                #pragma unroll
                for (int j = 0; j < 8; ++j)
                    acc[i][j] = fmaf(a[i], b[j], acc[i][j]);
        }
        __syncthreads();
    }
    #pragma unroll
    for (int i = 0; i < 8; ++i) {
        float* Crow = C + (size_t)(bm + ty*8 + i) * N + bn + tx*8;
        #pragma unroll
        for (int j = 0; j < 8; ++j) Crow[j] = acc[i][j] + bias[bn + tx*8 + j];
    }
}

// =====================================================================
// Kernel 2: RMSNorm(q,k) + RoPE + transpose to [B,H,L,D]; copy v.
// One block (128 threads) per (b,l,h) triple.
// =====================================================================
__global__ __launch_bounds__(128) void qkv_post(
    const float* __restrict__ pe, const float* __restrict__ qscale,
    const float* __restrict__ kscale)
{
    __shared__ float sq[128], sk[128], qs[128], ks[128];
    const int idx = blockIdx.x;
    const int h = idx % HEADS;
    const int l = (idx / HEADS) % LL;
    const int b = idx / (HEADS * LL);
    const int d = threadIdx.x;

    const size_t row = (size_t)(b * LL + l) * NQKV;
    float qv = g_qkv[row +            h*HD + d];
    float kv = g_qkv[row + DIM      + h*HD + d];
    float vv = g_qkv[row + 2*DIM    + h*HD + d];

    sq[d] = qv * qv; sk[d] = kv * kv;
    __syncthreads();
    for (int off = 64; off > 0; off >>= 1) {
        if (d < off) { sq[d] += sq[d+off]; sk[d] += sk[d+off]; }
        __syncthreads();
    }
    float rq = rsqrtf(sq[0] * (1.f/HD) + 1e-6f);
    float rk = rsqrtf(sk[0] * (1.f/HD) + 1e-6f);
    qs[d] = qv * rq * qscale[d];
    ks[d] = kv * rk * kscale[d];
    __syncthreads();

    const int p = d >> 1, r = d & 1;
    const float* pe4 = pe + (((size_t)l * 64 + p) * 2 + r) * 2;
    float qo = pe4[0]*qs[2*p] + pe4[1]*qs[2*p+1];
    float ko = pe4[0]*ks[2*p] + pe4[1]*ks[2*p+1];

    const size_t ob = ((size_t)(b*HEADS + h) * LL + l) * HD + d;
    g_q[ob] = qo; g_k[ob] = ko; g_v[ob] = vv;
}

// =====================================================================
// Kernel 3: flash attention (fp32, online softmax). BM=BN=64, D=128.
// grid: (L/64, B*H). 256 threads = 16x16. K and V share one smem buffer.
// =====================================================================
#define FA_BM 64
#define FA_BN 64
#define PQ 132        // padded row stride for Q/KV tiles (mult of 4 -> float4 ok)
#define PS 68         // padded row stride for P tile

__global__ __launch_bounds__(256) void flash_attn()
{
    extern __shared__ float sm[];
    float* Qs  = sm;                       // [64][132]
    float* KVs = sm + FA_BM * PQ;          // [64][132]
    float* Ps  = sm + 2 * FA_BM * PQ;      // [64][68]

    const int tid = threadIdx.x;
    const int tx = tid & 15, ty = tid >> 4;
    const int bh = blockIdx.y;             // b*HEADS + h
    const int qt = blockIdx.x;

    const float* qptr = g_q + ((size_t)bh * LL + qt * FA_BM) * HD;
    const float* kptr = g_k + (size_t)bh * LL * HD;
    const float* vptr = g_v + (size_t)bh * LL * HD;

    const int r0 = tid >> 5;               // 0..7
    const int c4 = (tid & 31) << 2;        // 0..124

    #pragma unroll
    for (int hh = 0; hh < 8; ++hh) {
        int rr = r0 + hh * 8;
        *(float4*)(Qs + rr*PQ + c4) = *(const float4*)(qptr + (size_t)rr*HD + c4);
    }

    float acc[4][8];
    #pragma unroll
    for (int i = 0; i < 4; ++i)
        #pragma unroll
        for (int j = 0; j < 8; ++j) acc[i][j] = 0.f;
    float mrow[4], lrow[4];
    #pragma unroll
    for (int i = 0; i < 4; ++i) { mrow[i] = -INFINITY; lrow[i] = 0.f; }
    const float scale = 0.08838834764831845f;   // 1/sqrt(128)

    for (int t = 0; t < LL / FA_BN; ++t) {
        __syncthreads();    // prev PV done reading KVs/Ps; Qs ready on t=0
        #pragma unroll
        for (int hh = 0; hh < 8; ++hh) {
            int rr = r0 + hh * 8;
            *(float4*)(KVs + rr*PQ + c4) =
                *(const float4*)(kptr + ((size_t)t*FA_BN + rr)*HD + c4);
        }
        __syncthreads();

        // S = Q K^T : thread owns rows ty*4+i, cols tx+16*j
        float s[4][4];
        #pragma unroll
        for (int i = 0; i < 4; ++i)
            #pragma unroll
            for (int j = 0; j < 4; ++j) s[i][j] = 0.f;
        for (int d = 0; d < HD; d += 4) {
            float4 qf[4], kf[4];
            #pragma unroll
            for (int i = 0; i < 4; ++i) qf[i] = *(const float4*)(Qs  + (ty*4+i)*PQ + d);
            #pragma unroll
            for (int j = 0; j < 4; ++j) kf[j] = *(const float4*)(KVs + (tx+16*j)*PQ + d);
            #pragma unroll
            for (int i = 0; i < 4; ++i)
                #pragma unroll
                for (int j = 0; j < 4; ++j) {
                    s[i][j] = fmaf(qf[i].x, kf[j].x, s[i][j]);
                    s[i][j] = fmaf(qf[i].y, kf[j].y, s[i][j]);
                    s[i][j] = fmaf(qf[i].z, kf[j].z, s[i][j]);
                    s[i][j] = fmaf(qf[i].w, kf[j].w, s[i][j]);
                }
        }

        // online softmax (rows reduced across the 16 tx lanes; result replicated)
        float alpha[4];
        #pragma unroll
        for (int i = 0; i < 4; ++i) {
            float mx = -INFINITY;
            #pragma unroll
            for (int j = 0; j < 4; ++j) { s[i][j] *= scale; mx = fmaxf(mx, s[i][j]); }
            #pragma unroll
            for (int o = 8; o >= 1; o >>= 1)
                mx = fmaxf(mx, __shfl_xor_sync(0xffffffffu, mx, o));
            float mn = fmaxf(mrow[i], mx);
            alpha[i] = __expf(mrow[i] - mn);
            mrow[i] = mn;
            float rs = 0.f;
            #pragma unroll
            for (int j = 0; j < 4; ++j) { s[i][j] = __expf(s[i][j] - mn); rs += s[i][j]; }
            #pragma unroll
            for (int o = 8; o >= 1; o >>= 1)
                rs += __shfl_xor_sync(0xffffffffu, rs, o);
            lrow[i] = lrow[i] * alpha[i] + rs;
            #pragma unroll
            for (int j = 0; j < 8; ++j) acc[i][j] *= alpha[i];
        }

        __syncthreads();    // everyone done reading K tile
        #pragma unroll
        for (int hh = 0; hh < 8; ++hh) {
            int rr = r0 + hh * 8;
            *(float4*)(KVs + rr*PQ + c4) =
                *(const float4*)(vptr + ((size_t)t*FA_BN + rr)*HD + c4);
        }
        #pragma unroll
        for (int i = 0; i < 4; ++i)
            #pragma unroll
            for (int j = 0; j < 4; ++j)
                Ps[(ty*4+i)*PS + tx + 16*j] = s[i][j];
        __syncthreads();    // V + P ready

        // O += P * V : thread rows ty*4+i, cols tx*8..tx*8+7
        #pragma unroll 4
        for (int n = 0; n < FA_BN; ++n) {
            float4 v0 = *(const float4*)(KVs + n*PQ + tx*8);
            float4 v1 = *(const float4*)(KVs + n*PQ + tx*8 + 4);
            #pragma unroll
            for (int i = 0; i < 4; ++i) {
                float pvi = Ps[(ty*4+i)*PS + n];
                acc[i][0] = fmaf(pvi, v0.x, acc[i][0]);
                acc[i][1] = fmaf(pvi, v0.y, acc[i][1]);
                acc[i][2] = fmaf(pvi, v0.z, acc[i][2]);
                acc[i][3] = fmaf(pvi, v0.w, acc[i][3]);
                acc[i][4] = fmaf(pvi, v1.x, acc[i][4]);
                acc[i][5] = fmaf(pvi, v1.y, acc[i][5]);
                acc[i][6] = fmaf(pvi, v1.z, acc[i][6]);
                acc[i][7] = fmaf(pvi, v1.w, acc[i][7]);
            }
        }
    }

    // write O in [B, L, H*D] layout (ready for the proj GEMM)
    const int b = bh / HEADS, h = bh % HEADS;
    #pragma unroll
    for (int i = 0; i < 4; ++i) {
        float inv = 1.f / lrow[i];
        int qrow = qt * FA_BM + ty*4 + i;
        float* orow = g_att + (size_t)(b*LL + qrow) * DIM + h*HD + tx*8;
        float4 o0 = make_float4(acc[i][0]*inv, acc[i][1]*inv, acc[i][2]*inv, acc[i][3]*inv);
        float4 o1 = make_float4(acc[i][4]*inv, acc[i][5]*inv, acc[i][6]*inv, acc[i][7]*inv);
        *(float4*)orow = o0;
        *(float4*)(orow + 4) = o1;
    }
}

// =====================================================================
// launch
// =====================================================================
extern "C" void kernel_launch(void* const* d_in, const int* in_sizes, int n_in,
                              void* d_out, int out_size)
{
    const float* x      = (const float*)d_in[0];
    const float* pe     = (const float*)d_in[1];
    const float* Wqkv   = (const float*)d_in[2];
    const float* bqkv   = (const float*)d_in[3];
    const float* qscale = (const float*)d_in[4];
    const float* kscale = (const float*)d_in[5];
    const float* Wproj  = (const float*)d_in[6];
    const float* bproj  = (const float*)d_in[7];
    float* out = (float*)d_out;

    float *qkv_p, *att_p;
    cudaGetSymbolAddress((void**)&qkv_p, g_qkv);
    cudaGetSymbolAddress((void**)&att_p, g_att);

    // 1) QKV GEMM: [4096,3072] x [9216,3072]^T + b -> g_qkv
    gemm_nt_bias<<<dim3(NQKV/128, MTOT/128), 256>>>(x, Wqkv, bqkv, qkv_p, NQKV, DIM);

    // 2) RMSNorm + RoPE + transpose -> g_q/g_k/g_v
    qkv_post<<<BB*LL*HEADS, 128>>>(pe, qscale, kscale);

    // 3) flash attention -> g_att in [B,L,DIM]
    size_t smem = (size_t)(2*FA_BM*PQ + FA_BM*PS) * sizeof(float);   // 84992 B
    cudaFuncSetAttribute(flash_attn, cudaFuncAttributeMaxDynamicSharedMemorySize,
                         (int)smem);
    flash_attn<<<dim3(LL/FA_BM, BB*HEADS), 256, smem>>>();

    // 4) proj GEMM: [4096,3072] x [3072,3072]^T + b -> out
    gemm_nt_bias<<<dim3(DIM/128, MTOT/128), 256>>>(att_p, Wproj, bproj, out, DIM, DIM);
}

// round 3
// speedup vs baseline: 1.5218x; 1.5218x over previous
#include <cuda_runtime.h>
#include <cuda_bf16.h>
#include <cstdint>
#include <math.h>

#define DIM   3072
#define HEADS 24
#define HD    128
#define BB    2
#define LL    2048
#define MTOT  (BB*LL)          // 4096 rows
#define NQKV  (3*DIM)          // 9216

// ---------------- scratch (static device globals; no runtime alloc) ----------------
__device__ float g_qkv[(size_t)MTOT * NQKV];        // [B*L, 3*DIM]
__device__ float g_q  [(size_t)BB*HEADS*LL*HD];     // [B,H,L,D]
__device__ float g_k  [(size_t)BB*HEADS*LL*HD];
__device__ float g_v  [(size_t)BB*HEADS*LL*HD];
__device__ float g_att[(size_t)MTOT * DIM];         // [B,L,DIM]

__device__ __nv_bfloat16 g_xhi [(size_t)MTOT * DIM];
__device__ __nv_bfloat16 g_xlo [(size_t)MTOT * DIM];
__device__ __nv_bfloat16 g_wqhi[(size_t)NQKV * DIM];
__device__ __nv_bfloat16 g_wqlo[(size_t)NQKV * DIM];
__device__ __nv_bfloat16 g_wphi[(size_t)DIM * DIM];
__device__ __nv_bfloat16 g_wplo[(size_t)DIM * DIM];
__device__ __nv_bfloat16 g_ahi [(size_t)MTOT * DIM];
__device__ __nv_bfloat16 g_alo [(size_t)MTOT * DIM];

// ====================== helpers ======================
__device__ __forceinline__ uint32_t smem_to_u32(const void* p) {
    uint32_t a;
    asm("{ .reg .u64 t; cvta.to.shared.u64 t, %1; cvt.u32.u64 %0, t; }" : "=r"(a) : "l"(p));
    return a;
}
__device__ __forceinline__ void cp16(uint32_t s, const void* g) {
    asm volatile("cp.async.cg.shared.global [%0], [%1], 16;\n" :: "r"(s), "l"(g));
}
#define CP_COMMIT() asm volatile("cp.async.commit_group;\n" ::: "memory")
#define CP_WAIT1()  asm volatile("cp.async.wait_group 1;\n" ::: "memory")
#define CP_WAIT0()  asm volatile("cp.async.wait_group 0;\n" ::: "memory")

__device__ __forceinline__ void ldmat4(uint32_t* r, uint32_t addr) {
    asm volatile("ldmatrix.sync.aligned.m8n8.x4.shared.b16 {%0,%1,%2,%3}, [%4];"
                 : "=r"(r[0]), "=r"(r[1]), "=r"(r[2]), "=r"(r[3]) : "r"(addr));
}
__device__ __forceinline__ void mma16816(float* d, const uint32_t* a,
                                         const uint32_t* b, const float* c) {
    asm volatile("mma.sync.aligned.m16n8k16.row.col.f32.bf16.bf16.f32 "
                 "{%0,%1,%2,%3}, {%4,%5,%6,%7}, {%8,%9}, {%10,%11,%12,%13};"
                 : "=f"(d[0]), "=f"(d[1]), "=f"(d[2]), "=f"(d[3])
                 : "r"(a[0]), "r"(a[1]), "r"(a[2]), "r"(a[3]),
                   "r"(b[0]), "r"(b[1]),
                   "f"(c[0]), "f"(c[1]), "f"(c[2]), "f"(c[3]));
}

// =====================================================================
// fp32 -> (bf16 hi, bf16 lo) split
// =====================================================================
__global__ __launch_bounds__(256) void split_bf16(
    const float* __restrict__ in, __nv_bfloat16* __restrict__ hi,
    __nv_bfloat16* __restrict__ lo, size_t n)
{
    for (size_t i = (size_t)blockIdx.x * blockDim.x + threadIdx.x; i < n;
         i += (size_t)gridDim.x * blockDim.x) {
        float v = in[i];
        __nv_bfloat16 h = __float2bfloat16(v);
        float r = v - __bfloat162float(h);
        hi[i] = h;
        lo[i] = __float2bfloat16(r);
    }
}

// =====================================================================
// mma.sync split-bf16 GEMM:  C[M,N] = A[M,K] @ B[N,K]^T + bias
// CTA 128x128, 8 warps (2m x 4n), warp tile 64x32, K-chunk 32,
// cp.async double buffer, XOR-swizzled smem for ldmatrix.
// =====================================================================
#define BK 32
#define TILE_B 8192            // 128 rows * 64 bytes (32 bf16)
#define STAGE_B (4*TILE_B)     // Ahi, Alo, Bhi, Blo

// smem byte address of (row, 16B-seg) inside a tile (4 segs per row)
__device__ __forceinline__ uint32_t swz(uint32_t row, uint32_t seg) {
    return row * 64u + ((seg ^ (row & 3u)) * 16u);
}

__global__ __launch_bounds__(256, 1) void gemm_split(
    const __nv_bfloat16* __restrict__ Ahi, const __nv_bfloat16* __restrict__ Alo,
    const __nv_bfloat16* __restrict__ Bhi, const __nv_bfloat16* __restrict__ Blo,
    const float* __restrict__ bias, float* __restrict__ C, int N, int K)
{
    extern __shared__ __align__(128) char smem[];
    const uint32_t sb = smem_to_u32(smem);
    const int tid = threadIdx.x;
    const int wid = tid >> 5, lane = tid & 31;
    const int wm = wid & 1, wn = wid >> 1;          // 2 x 4 warp grid
    const int bm = blockIdx.y * 128, bn = blockIdx.x * 128;

    const __nv_bfloat16* src[4] = { Ahi + (size_t)bm * K, Alo + (size_t)bm * K,
                                    Bhi + (size_t)bn * K, Blo + (size_t)bn * K };

    // cp.async: 512 16B-segs per tile, 256 threads -> 2 segs/thread/tile
    const uint32_t seg0 = (uint32_t)tid * 2;
    const uint32_t r0 = seg0 >> 2, ks0 = seg0 & 3;        // seg0, seg0+1 same row
    // prologue: chunk 0 -> stage 0
    #pragma unroll
    for (int t = 0; t < 4; ++t) {
        uint32_t dst = sb + (uint32_t)t * TILE_B;
        const __nv_bfloat16* g = src[t] + (size_t)r0 * K;
        cp16(dst + swz(r0, ks0),     g + ks0 * 8);
        cp16(dst + swz(r0, ks0 + 1), g + ks0 * 8 + 8);
    }
    CP_COMMIT();

    float acc[4][4][4];
    #pragma unroll
    for (int i = 0; i < 4; ++i)
        #pragma unroll
        for (int j = 0; j < 4; ++j)
            #pragma unroll
            for (int e = 0; e < 4; ++e) acc[i][j][e] = 0.f;

    // ldmatrix lane addressing (within a 128x32 tile)
    const uint32_t a_row = (uint32_t)(wm * 64 + (lane & 15));      // + mi*16
    const uint32_t a_seg = (uint32_t)(lane >> 4);                  // + ks*2
    const uint32_t b_row = (uint32_t)(wn * 32 + ((lane >> 4) << 3) + (lane & 7)); // + njp*16
    const uint32_t b_seg = (uint32_t)((lane >> 3) & 1);            // + ks*2

    const int nchunk = K / BK;
    for (int t = 0; t < nchunk; ++t) {
        const uint32_t cur = (uint32_t)(t & 1) * STAGE_B;
        if (t + 1 < nchunk) {
            const uint32_t nxt = (uint32_t)((t + 1) & 1) * STAGE_B;
            const int k0 = (t + 1) * BK;
            #pragma unroll
            for (int tt = 0; tt < 4; ++tt) {
                uint32_t dst = sb + nxt + (uint32_t)tt * TILE_B;
                const __nv_bfloat16* g = src[tt] + (size_t)r0 * K + k0;
                cp16(dst + swz(r0, ks0),     g + ks0 * 8);
                cp16(dst + swz(r0, ks0 + 1), g + ks0 * 8 + 8);
            }
            CP_COMMIT();
            CP_WAIT1();
        } else {
            CP_WAIT0();
        }
        __syncthreads();

        const uint32_t Ah = sb + cur;
        const uint32_t Al = Ah + TILE_B;
        const uint32_t Bh = Al + TILE_B;
        const uint32_t Bl = Bh + TILE_B;

        #pragma unroll
        for (int ks = 0; ks < 2; ++ks) {
            uint32_t ah[4][4], al[4][4], bh[4][2], bl[4][2];
            #pragma unroll
            for (int mi = 0; mi < 4; ++mi) {
                uint32_t row = a_row + mi * 16;
                uint32_t seg = a_seg + ks * 2;
                ldmat4(ah[mi], Ah + swz(row, seg));
                ldmat4(al[mi], Al + swz(row, seg));
            }
            #pragma unroll
            for (int njp = 0; njp < 2; ++njp) {
                uint32_t row = b_row + njp * 16;
                uint32_t seg = b_seg + ks * 2;
                uint32_t rb[4];
                ldmat4(rb, Bh + swz(row, seg));
                bh[njp*2][0] = rb[0]; bh[njp*2][1] = rb[1];
                bh[njp*2+1][0] = rb[2]; bh[njp*2+1][1] = rb[3];
                ldmat4(rb, Bl + swz(row, seg));
                bl[njp*2][0] = rb[0]; bl[njp*2][1] = rb[1];
                bl[njp*2+1][0] = rb[2]; bl[njp*2+1][1] = rb[3];
            }
            #pragma unroll
            for (int mi = 0; mi < 4; ++mi)
                #pragma unroll
                for (int nj = 0; nj < 4; ++nj) {
                    mma16816(acc[mi][nj], ah[mi], bh[nj], acc[mi][nj]);
                    mma16816(acc[mi][nj], ah[mi], bl[nj], acc[mi][nj]);
                    mma16816(acc[mi][nj], al[mi], bh[nj], acc[mi][nj]);
                }
        }
        __syncthreads();
    }

    // epilogue: D rows wm*64+mi*16+g (+8), cols wn*32+nj*8+2tc
    const int g = lane >> 2, tc = lane & 3;
    #pragma unroll
    for (int mi = 0; mi < 4; ++mi) {
        int row = bm + wm * 64 + mi * 16 + g;
        #pragma unroll
        for (int nj = 0; nj < 4; ++nj) {
            int col = bn + wn * 32 + nj * 8 + tc * 2;
            float b0 = bias[col], b1 = bias[col + 1];
            float2 v0 = make_float2(acc[mi][nj][0] + b0, acc[mi][nj][1] + b1);
            float2 v1 = make_float2(acc[mi][nj][2] + b0, acc[mi][nj][3] + b1);
            *(float2*)(C + (size_t)row * N + col) = v0;
            *(float2*)(C + (size_t)(row + 8) * N + col) = v1;
        }
    }
}

// =====================================================================
// RMSNorm(q,k) + RoPE + transpose to [B,H,L,D]; copy v.
// =====================================================================
__global__ __launch_bounds__(128) void qkv_post(
    const float* __restrict__ pe, const float* __restrict__ qscale,
    const float* __restrict__ kscale)
{
    __shared__ float sq[128], sk[128], qs[128], ks[128];
    const int idx = blockIdx.x;
    const int h = idx % HEADS;
    const int l = (idx / HEADS) % LL;
    const int b = idx / (HEADS * LL);
    const int d = threadIdx.x;

    const size_t row = (size_t)(b * LL + l) * NQKV;
    float qv = g_qkv[row +           h*HD + d];
    float kv = g_qkv[row + DIM     + h*HD + d];
    float vv = g_qkv[row + 2*DIM   + h*HD + d];

    sq[d] = qv * qv; sk[d] = kv * kv;
    __syncthreads();
    for (int off = 64; off > 0; off >>= 1) {
        if (d < off) { sq[d] += sq[d+off]; sk[d] += sk[d+off]; }
        __syncthreads();
    }
    float rq = rsqrtf(sq[0] * (1.f/HD) + 1e-6f);
    float rk = rsqrtf(sk[0] * (1.f/HD) + 1e-6f);
    qs[d] = qv * rq * qscale[d];
    ks[d] = kv * rk * kscale[d];
    __syncthreads();

    const int p = d >> 1, r = d & 1;
    const float* pe4 = pe + (((size_t)l * 64 + p) * 2 + r) * 2;
    float qo = pe4[0]*qs[2*p] + pe4[1]*qs[2*p+1];
    float ko = pe4[0]*ks[2*p] + pe4[1]*ks[2*p+1];

    const size_t ob = ((size_t)(b*HEADS + h) * LL + l) * HD + d;
    g_q[ob] = qo; g_k[ob] = ko; g_v[ob] = vv;
}

// =====================================================================
// flash attention (fp32, online softmax). BM=BN=64, D=128.
// =====================================================================
#define FA_BM 64
#define FA_BN 64
#define PQ 132
#define PS 68

__global__ __launch_bounds__(256) void flash_attn()
{
    extern __shared__ float sm[];
    float* Qs  = sm;
    float* KVs = sm + FA_BM * PQ;
    float* Ps  = sm + 2 * FA_BM * PQ;

    const int tid = threadIdx.x;
    const int tx = tid & 15, ty = tid >> 4;
    const int bh = blockIdx.y;
    const int qt = blockIdx.x;

    const float* qptr = g_q + ((size_t)bh * LL + qt * FA_BM) * HD;
    const float* kptr = g_k + (size_t)bh * LL * HD;
    const float* vptr = g_v + (size_t)bh * LL * HD;

    const int r0 = tid >> 5;
    const int c4 = (tid & 31) << 2;

    #pragma unroll
    for (int hh = 0; hh < 8; ++hh) {
        int rr = r0 + hh * 8;
        *(float4*)(Qs + rr*PQ + c4) = *(const float4*)(qptr + (size_t)rr*HD + c4);
    }

    float acc[4][8];
    #pragma unroll
    for (int i = 0; i < 4; ++i)
        #pragma unroll
        for (int j = 0; j < 8; ++j) acc[i][j] = 0.f;
    float mrow[4], lrow[4];
    #pragma unroll
    for (int i = 0; i < 4; ++i) { mrow[i] = -INFINITY; lrow[i] = 0.f; }
    const float scale = 0.08838834764831845f;

    for (int t = 0; t < LL / FA_BN; ++t) {
        __syncthreads();
        #pragma unroll
        for (int hh = 0; hh < 8; ++hh) {
            int rr = r0 + hh * 8;
            *(float4*)(KVs + rr*PQ + c4) =
                *(const float4*)(kptr + ((size_t)t*FA_BN + rr)*HD + c4);
        }
        __syncthreads();

        float s[4][4];
        #pragma unroll
        for (int i = 0; i < 4; ++i)
            #pragma unroll
            for (int j = 0; j < 4; ++j) s[i][j] = 0.f;
        for (int d = 0; d < HD; d += 4) {
            float4 qf[4], kf[4];
            #pragma unroll
            for (int i = 0; i < 4; ++i) qf[i] = *(const float4*)(Qs  + (ty*4+i)*PQ + d);
            #pragma unroll
            for (int j = 0; j < 4; ++j) kf[j] = *(const float4*)(KVs + (tx+16*j)*PQ + d);
            #pragma unroll
            for (int i = 0; i < 4; ++i)
                #pragma unroll
                for (int j = 0; j < 4; ++j) {
                    s[i][j] = fmaf(qf[i].x, kf[j].x, s[i][j]);
                    s[i][j] = fmaf(qf[i].y, kf[j].y, s[i][j]);
                    s[i][j] = fmaf(qf[i].z, kf[j].z, s[i][j]);
                    s[i][j] = fmaf(qf[i].w, kf[j].w, s[i][j]);
                }
        }

        float alpha[4];
        #pragma unroll
        for (int i = 0; i < 4; ++i) {
            float mx = -INFINITY;
            #pragma unroll
            for (int j = 0; j < 4; ++j) { s[i][j] *= scale; mx = fmaxf(mx, s[i][j]); }
            #pragma unroll
            for (int o = 8; o >= 1; o >>= 1)
                mx = fmaxf(mx, __shfl_xor_sync(0xffffffffu, mx, o));
            float mn = fmaxf(mrow[i], mx);
            alpha[i] = __expf(mrow[i] - mn);
            mrow[i] = mn;
            float rs = 0.f;
            #pragma unroll
            for (int j = 0; j < 4; ++j) { s[i][j] = __expf(s[i][j] - mn); rs += s[i][j]; }
            #pragma unroll
            for (int o = 8; o >= 1; o >>= 1)
                rs += __shfl_xor_sync(0xffffffffu, rs, o);
            lrow[i] = lrow[i] * alpha[i] + rs;
            #pragma unroll
            for (int j = 0; j < 8; ++j) acc[i][j] *= alpha[i];
        }

        __syncthreads();
        #pragma unroll
        for (int hh = 0; hh < 8; ++hh) {
            int rr = r0 + hh * 8;
            *(float4*)(KVs + rr*PQ + c4) =
                *(const float4*)(vptr + ((size_t)t*FA_BN + rr)*HD + c4);
        }
        #pragma unroll
        for (int i = 0; i < 4; ++i)
            #pragma unroll
            for (int j = 0; j < 4; ++j)
                Ps[(ty*4+i)*PS + tx + 16*j] = s[i][j];
        __syncthreads();

        #pragma unroll 4
        for (int n = 0; n < FA_BN; ++n) {
            float4 v0 = *(const float4*)(KVs + n*PQ + tx*8);
            float4 v1 = *(const float4*)(KVs + n*PQ + tx*8 + 4);
            #pragma unroll
            for (int i = 0; i < 4; ++i) {
                float pvi = Ps[(ty*4+i)*PS + n];
                acc[i][0] = fmaf(pvi, v0.x, acc[i][0]);
                acc[i][1] = fmaf(pvi, v0.y, acc[i][1]);
                acc[i][2] = fmaf(pvi, v0.z, acc[i][2]);
                acc[i][3] = fmaf(pvi, v0.w, acc[i][3]);
                acc[i][4] = fmaf(pvi, v1.x, acc[i][4]);
                acc[i][5] = fmaf(pvi, v1.y, acc[i][5]);
                acc[i][6] = fmaf(pvi, v1.z, acc[i][6]);
                acc[i][7] = fmaf(pvi, v1.w, acc[i][7]);
            }
        }
    }

    const int b = bh / HEADS, h = bh % HEADS;
    #pragma unroll
    for (int i = 0; i < 4; ++i) {
        float inv = 1.f / lrow[i];
        int qrow = qt * FA_BM + ty*4 + i;
        float* orow = g_att + (size_t)(b*LL + qrow) * DIM + h*HD + tx*8;
        float4 o0 = make_float4(acc[i][0]*inv, acc[i][1]*inv, acc[i][2]*inv, acc[i][3]*inv);
        float4 o1 = make_float4(acc[i][4]*inv, acc[i][5]*inv, acc[i][6]*inv, acc[i][7]*inv);
        *(float4*)orow = o0;
        *(float4*)(orow + 4) = o1;
    }
}

// =====================================================================
// launch
// =====================================================================
extern "C" void kernel_launch(void* const* d_in, const int* in_sizes, int n_in,
                              void* d_out, int out_size)
{
    const float* x      = (const float*)d_in[0];
    const float* pe     = (const float*)d_in[1];
    const float* Wqkv   = (const float*)d_in[2];
    const float* bqkv   = (const float*)d_in[3];
    const float* qscale = (const float*)d_in[4];
    const float* kscale = (const float*)d_in[5];
    const float* Wproj  = (const float*)d_in[6];
    const float* bproj  = (const float*)d_in[7];
    float* out = (float*)d_out;

    float *qkv_p, *att_p;
    cudaGetSymbolAddress((void**)&qkv_p, g_qkv);
    cudaGetSymbolAddress((void**)&att_p, g_att);
    __nv_bfloat16 *xhi, *xlo, *wqhi, *wqlo, *wphi, *wplo, *ahi, *alo;
    cudaGetSymbolAddress((void**)&xhi,  g_xhi);
    cudaGetSymbolAddress((void**)&xlo,  g_xlo);
    cudaGetSymbolAddress((void**)&wqhi, g_wqhi);
    cudaGetSymbolAddress((void**)&wqlo, g_wqlo);
    cudaGetSymbolAddress((void**)&wphi, g_wphi);
    cudaGetSymbolAddress((void**)&wplo, g_wplo);
    cudaGetSymbolAddress((void**)&ahi,  g_ahi);
    cudaGetSymbolAddress((void**)&alo,  g_alo);

    const size_t smem_gemm = 2 * (size_t)STAGE_B;   // 64 KB
    cudaFuncSetAttribute(gemm_split, cudaFuncAttributeMaxDynamicSharedMemorySize,
                         (int)smem_gemm);

    // 0) bf16 splits of x and Wqkv
    split_bf16<<<2048, 256>>>(x,    xhi,  xlo,  (size_t)MTOT * DIM);
    split_bf16<<<2048, 256>>>(Wqkv, wqhi, wqlo, (size_t)NQKV * DIM);

    // 1) QKV GEMM (mma.sync): [4096,3072] x [9216,3072]^T + b -> g_qkv (fp32)
    gemm_split<<<dim3(NQKV/128, MTOT/128), 256, smem_gemm>>>(
        xhi, xlo, wqhi, wqlo, bqkv, qkv_p, NQKV, DIM);

    // 2) RMSNorm + RoPE + transpose
    qkv_post<<<BB*LL*HEADS, 128>>>(pe, qscale, kscale);

    // 3) flash attention (fp32) -> g_att
    size_t smem_fa = (size_t)(2*FA_BM*PQ + FA_BM*PS) * sizeof(float);
    cudaFuncSetAttribute(flash_attn, cudaFuncAttributeMaxDynamicSharedMemorySize,
                         (int)smem_fa);
    flash_attn<<<dim3(LL/FA_BM, BB*HEADS), 256, smem_fa>>>();

    // 4) bf16 splits of attention output and Wproj
    split_bf16<<<2048, 256>>>(att_p, ahi,  alo,  (size_t)MTOT * DIM);
    split_bf16<<<2048, 256>>>(Wproj, wphi, wplo, (size_t)DIM * DIM);

    // 5) proj GEMM (mma.sync): [4096,3072] x [3072,3072]^T + b -> out
    gemm_split<<<dim3(DIM/128, MTOT/128), 256, smem_gemm>>>(
        ahi, alo, wphi, wplo, bproj, out, DIM, DIM);
}

// round 5
// speedup vs baseline: 2.0379x; 1.3391x over previous
#include <cuda_runtime.h>
#include <cuda_bf16.h>
#include <cstdint>
#include <math.h>

#define DIM   3072
#define HEADS 24
#define HD    128
#define BB    2
#define LL    2048
#define MTOT  (BB*LL)          // 4096 rows
#define NQKV  (3*DIM)          // 9216
#define BH    (BB*HEADS)       // 48

// ---------------- scratch (static device globals; no runtime alloc) ----------------
__device__ float g_qkv[(size_t)MTOT * NQKV];        // [B*L, 3*DIM]

__device__ __nv_bfloat16 g_xhi [(size_t)MTOT * DIM];
__device__ __nv_bfloat16 g_xlo [(size_t)MTOT * DIM];
__device__ __nv_bfloat16 g_wqhi[(size_t)NQKV * DIM];
__device__ __nv_bfloat16 g_wqlo[(size_t)NQKV * DIM];
__device__ __nv_bfloat16 g_wphi[(size_t)DIM * DIM];
__device__ __nv_bfloat16 g_wplo[(size_t)DIM * DIM];
__device__ __nv_bfloat16 g_ahi [(size_t)MTOT * DIM];   // attention out hi
__device__ __nv_bfloat16 g_alo [(size_t)MTOT * DIM];   // attention out lo

__device__ __nv_bfloat16 g_qhi [(size_t)BH*LL*HD];  // [BH, L, D]
__device__ __nv_bfloat16 g_qlo [(size_t)BH*LL*HD];
__device__ __nv_bfloat16 g_khi [(size_t)BH*LL*HD];
__device__ __nv_bfloat16 g_klo [(size_t)BH*LL*HD];
__device__ __nv_bfloat16 g_vthi[(size_t)BH*HD*LL];  // [BH, D, L] (transposed)
__device__ __nv_bfloat16 g_vtlo[(size_t)BH*HD*LL];

// ====================== helpers ======================
__device__ __forceinline__ uint32_t smem_to_u32(const void* p) {
    uint32_t a;
    asm("{ .reg .u64 t; cvta.to.shared.u64 t, %1; cvt.u32.u64 %0, t; }" : "=r"(a) : "l"(p));
    return a;
}
__device__ __forceinline__ void cp16(uint32_t s, const void* g) {
    asm volatile("cp.async.cg.shared.global [%0], [%1], 16;\n" :: "r"(s), "l"(g));
}
#define CP_COMMIT() asm volatile("cp.async.commit_group;\n" ::: "memory")
#define CP_WAIT1()  asm volatile("cp.async.wait_group 1;\n" ::: "memory")
#define CP_WAIT0()  asm volatile("cp.async.wait_group 0;\n" ::: "memory")

__device__ __forceinline__ void ldmat4(uint32_t* r, uint32_t addr) {
    asm volatile("ldmatrix.sync.aligned.m8n8.x4.shared.b16 {%0,%1,%2,%3}, [%4];"
                 : "=r"(r[0]), "=r"(r[1]), "=r"(r[2]), "=r"(r[3]) : "r"(addr));
}
__device__ __forceinline__ void mma16816(float* d, const uint32_t* a,
                                         const uint32_t* b, const float* c) {
    asm volatile("mma.sync.aligned.m16n8k16.row.col.f32.bf16.bf16.f32 "
                 "{%0,%1,%2,%3}, {%4,%5,%6,%7}, {%8,%9}, {%10,%11,%12,%13};"
                 : "=f"(d[0]), "=f"(d[1]), "=f"(d[2]), "=f"(d[3])
                 : "r"(a[0]), "r"(a[1]), "r"(a[2]), "r"(a[3]),
                   "r"(b[0]), "r"(b[1]),
                   "f"(c[0]), "f"(c[1]), "f"(c[2]), "f"(c[3]));
}
__device__ __forceinline__ uint32_t pack2(float a, float b) {
    __nv_bfloat16 x = __float2bfloat16(a), y = __float2bfloat16(b);
    uint16_t ux = *(uint16_t*)&x, uy = *(uint16_t*)&y;
    return (uint32_t)ux | ((uint32_t)uy << 16);
}

// =====================================================================
// fp32 -> (bf16 hi, bf16 lo) split
// =====================================================================
__global__ __launch_bounds__(256) void split_bf16(
    const float* __restrict__ in, __nv_bfloat16* __restrict__ hi,
    __nv_bfloat16* __restrict__ lo, size_t n)
{
    for (size_t i = (size_t)blockIdx.x * blockDim.x + threadIdx.x; i < n;
         i += (size_t)gridDim.x * blockDim.x) {
        float v = in[i];
        __nv_bfloat16 h = __float2bfloat16(v);
        float r = v - __bfloat162float(h);
        hi[i] = h;
        lo[i] = __float2bfloat16(r);
    }
}

// =====================================================================
// mma.sync split-bf16 GEMM (validated round 3): C = A @ B^T + bias
// =====================================================================
#define BK 32
#define TILE_B 8192            // 128 rows * 64 bytes (32 bf16)
#define STAGE_B (4*TILE_B)

__device__ __forceinline__ uint32_t swz(uint32_t row, uint32_t seg) {
    return row * 64u + ((seg ^ (row & 3u)) * 16u);
}

__global__ __launch_bounds__(256, 1) void gemm_split(
    const __nv_bfloat16* __restrict__ Ahi, const __nv_bfloat16* __restrict__ Alo,
    const __nv_bfloat16* __restrict__ Bhi, const __nv_bfloat16* __restrict__ Blo,
    const float* __restrict__ bias, float* __restrict__ C, int N, int K)
{
    extern __shared__ __align__(128) char smem[];
    const uint32_t sb = smem_to_u32(smem);
    const int tid = threadIdx.x;
    const int wid = tid >> 5, lane = tid & 31;
    const int wm = wid & 1, wn = wid >> 1;
    const int bm = blockIdx.y * 128, bn = blockIdx.x * 128;

    const __nv_bfloat16* src[4] = { Ahi + (size_t)bm * K, Alo + (size_t)bm * K,
                                    Bhi + (size_t)bn * K, Blo + (size_t)bn * K };

    const uint32_t seg0 = (uint32_t)tid * 2;
    const uint32_t r0 = seg0 >> 2, ks0 = seg0 & 3;
    #pragma unroll
    for (int t = 0; t < 4; ++t) {
        uint32_t dst = sb + (uint32_t)t * TILE_B;
        const __nv_bfloat16* g = src[t] + (size_t)r0 * K;
        cp16(dst + swz(r0, ks0),     g + ks0 * 8);
        cp16(dst + swz(r0, ks0 + 1), g + ks0 * 8 + 8);
    }
    CP_COMMIT();

    float acc[4][4][4];
    #pragma unroll
    for (int i = 0; i < 4; ++i)
        #pragma unroll
        for (int j = 0; j < 4; ++j)
            #pragma unroll
            for (int e = 0; e < 4; ++e) acc[i][j][e] = 0.f;

    const uint32_t a_row = (uint32_t)(wm * 64 + (lane & 15));
    const uint32_t a_seg = (uint32_t)(lane >> 4);
    const uint32_t b_row = (uint32_t)(wn * 32 + ((lane >> 4) << 3) + (lane & 7));
    const uint32_t b_seg = (uint32_t)((lane >> 3) & 1);

    const int nchunk = K / BK;
    for (int t = 0; t < nchunk; ++t) {
        const uint32_t cur = (uint32_t)(t & 1) * STAGE_B;
        if (t + 1 < nchunk) {
            const uint32_t nxt = (uint32_t)((t + 1) & 1) * STAGE_B;
            const int k0 = (t + 1) * BK;
            #pragma unroll
            for (int tt = 0; tt < 4; ++tt) {
                uint32_t dst = sb + nxt + (uint32_t)tt * TILE_B;
                const __nv_bfloat16* g = src[tt] + (size_t)r0 * K + k0;
                cp16(dst + swz(r0, ks0),     g + ks0 * 8);
                cp16(dst + swz(r0, ks0 + 1), g + ks0 * 8 + 8);
            }
            CP_COMMIT();
            CP_WAIT1();
        } else {
            CP_WAIT0();
        }
        __syncthreads();

        const uint32_t Ah = sb + cur;
        const uint32_t Al = Ah + TILE_B;
        const uint32_t Bh = Al + TILE_B;
        const uint32_t Bl = Bh + TILE_B;

        #pragma unroll
        for (int ks = 0; ks < 2; ++ks) {
            uint32_t ah[4][4], al[4][4], bh[4][2], bl[4][2];
            #pragma unroll
            for (int mi = 0; mi < 4; ++mi) {
                uint32_t row = a_row + mi * 16;
                uint32_t seg = a_seg + ks * 2;
                ldmat4(ah[mi], Ah + swz(row, seg));
                ldmat4(al[mi], Al + swz(row, seg));
            }
            #pragma unroll
            for (int njp = 0; njp < 2; ++njp) {
                uint32_t row = b_row + njp * 16;
                uint32_t seg = b_seg + ks * 2;
                uint32_t rb[4];
                ldmat4(rb, Bh + swz(row, seg));
                bh[njp*2][0] = rb[0]; bh[njp*2][1] = rb[1];
                bh[njp*2+1][0] = rb[2]; bh[njp*2+1][1] = rb[3];
                ldmat4(rb, Bl + swz(row, seg));
                bl[njp*2][0] = rb[0]; bl[njp*2][1] = rb[1];
                bl[njp*2+1][0] = rb[2]; bl[njp*2+1][1] = rb[3];
            }
            #pragma unroll
            for (int mi = 0; mi < 4; ++mi)
                #pragma unroll
                for (int nj = 0; nj < 4; ++nj) {
                    mma16816(acc[mi][nj], ah[mi], bh[nj], acc[mi][nj]);
                    mma16816(acc[mi][nj], ah[mi], bl[nj], acc[mi][nj]);
                    mma16816(acc[mi][nj], al[mi], bh[nj], acc[mi][nj]);
                }
        }
        __syncthreads();
    }

    const int g = lane >> 2, tc = lane & 3;
    #pragma unroll
    for (int mi = 0; mi < 4; ++mi) {
        int row = bm + wm * 64 + mi * 16 + g;
        #pragma unroll
        for (int nj = 0; nj < 4; ++nj) {
            int col = bn + wn * 32 + nj * 8 + tc * 2;
            float b0 = bias[col], b1 = bias[col + 1];
            float2 v0 = make_float2(acc[mi][nj][0] + b0, acc[mi][nj][1] + b1);
            float2 v1 = make_float2(acc[mi][nj][2] + b0, acc[mi][nj][3] + b1);
            *(float2*)(C + (size_t)row * N + col) = v0;
            *(float2*)(C + (size_t)(row + 8) * N + col) = v1;
        }
    }
}

// =====================================================================
// RMSNorm(q,k) + RoPE; write q,k as bf16 hi/lo [BH,L,D]; v transposed
// as bf16 hi/lo [BH,D,L].
// =====================================================================
__global__ __launch_bounds__(128) void qkv_post(
    const float* __restrict__ pe, const float* __restrict__ qscale,
    const float* __restrict__ kscale)
{
    __shared__ float sq[128], sk[128], qs[128], ks[128];
    const int idx = blockIdx.x;
    const int h = idx % HEADS;
    const int l = (idx / HEADS) % LL;
    const int b = idx / (HEADS * LL);
    const int d = threadIdx.x;

    const size_t row = (size_t)(b * LL + l) * NQKV;
    float qv = g_qkv[row +           h*HD + d];
    float kv = g_qkv[row + DIM     + h*HD + d];
    float vv = g_qkv[row + 2*DIM   + h*HD + d];

    sq[d] = qv * qv; sk[d] = kv * kv;
    __syncthreads();
    for (int off = 64; off > 0; off >>= 1) {
        if (d < off) { sq[d] += sq[d+off]; sk[d] += sk[d+off]; }
        __syncthreads();
    }
    float rq = rsqrtf(sq[0] * (1.f/HD) + 1e-6f);
    float rk = rsqrtf(sk[0] * (1.f/HD) + 1e-6f);
    qs[d] = qv * rq * qscale[d];
    ks[d] = kv * rk * kscale[d];
    __syncthreads();

    const int p = d >> 1, r = d & 1;
    const float* pe4 = pe + (((size_t)l * 64 + p) * 2 + r) * 2;
    float qo = pe4[0]*qs[2*p] + pe4[1]*qs[2*p+1];
    float ko = pe4[0]*ks[2*p] + pe4[1]*ks[2*p+1];

    const int bh = b * HEADS + h;
    const size_t qk = ((size_t)bh * LL + l) * HD + d;
    __nv_bfloat16 qh = __float2bfloat16(qo);
    g_qhi[qk] = qh;  g_qlo[qk] = __float2bfloat16(qo - __bfloat162float(qh));
    __nv_bfloat16 kh = __float2bfloat16(ko);
    g_khi[qk] = kh;  g_klo[qk] = __float2bfloat16(ko - __bfloat162float(kh));
    const size_t vt = ((size_t)bh * HD + d) * LL + l;
    __nv_bfloat16 vh = __float2bfloat16(vv);
    g_vthi[vt] = vh; g_vtlo[vt] = __float2bfloat16(vv - __bfloat162float(vh));
}

// =====================================================================
// tensor-core flash attention (bf16 hi/lo split, online softmax)
// BM=64, BN=64, D=128, 8 warps.
// =====================================================================
#define SWZQ(r, s) ((r)*256u + ((uint32_t)((s) ^ ((r) & 7u)) * 16u))   // 256B rows
#define SWZV(r, s) ((r)*128u + ((uint32_t)((s) ^ ((r) & 7u)) * 16u))   // 128B rows

#define F_QHI 0
#define F_QLO 16384
#define F_KHI 32768      // 2 stages x 16384
#define F_KLO 65536
#define F_VHI 98304
#define F_VLO 131072
#define F_SS  163840     // fp32 [64][68] = 17408
#define F_PHI 181248
#define F_PLO 189440
#define F_MR  197632
#define F_LR  197888
#define F_AL  198144
#define F_TOT 198400

__global__ __launch_bounds__(256, 1) void flash_attn_mma()
{
    extern __shared__ __align__(128) char sm[];
    const uint32_t sb = smem_to_u32(sm);
    float* s_S  = (float*)(sm + F_SS);
    float* s_mr = (float*)(sm + F_MR);
    float* s_lr = (float*)(sm + F_LR);
    float* s_al = (float*)(sm + F_AL);

    const int tid = threadIdx.x, lane = tid & 31, wid = tid >> 5;
    const int wm = wid & 1, wn = wid >> 1;      // wn doubles as wd in PV phase
    const int bh = blockIdx.y, qt = blockIdx.x;
    const float scale = 0.08838834764831845f;   // 1/sqrt(128)

    if (tid < 64) { s_mr[tid] = -INFINITY; s_lr[tid] = 0.f; }

    // ---- prologue: Q tiles + KV stage 0 ----
    {
        const __nv_bfloat16* qh = g_qhi + ((size_t)bh * LL + (size_t)qt * 64) * HD;
        const __nv_bfloat16* ql = g_qlo + ((size_t)bh * LL + (size_t)qt * 64) * HD;
        uint32_t row = tid >> 2, s0 = (tid & 3) * 4;
        #pragma unroll
        for (int i = 0; i < 4; ++i) {
            cp16(sb + F_QHI + SWZQ(row, s0 + i), qh + (size_t)row * HD + (s0 + i) * 8);
            cp16(sb + F_QLO + SWZQ(row, s0 + i), ql + (size_t)row * HD + (s0 + i) * 8);
        }
    }
    {
        const int t = 0, stage = 0;
        const __nv_bfloat16* kh = g_khi + ((size_t)bh * LL + (size_t)t * 64) * HD;
        const __nv_bfloat16* kl = g_klo + ((size_t)bh * LL + (size_t)t * 64) * HD;
        uint32_t row = tid >> 2, s0 = (tid & 3) * 4;
        #pragma unroll
        for (int i = 0; i < 4; ++i) {
            cp16(sb + F_KHI + stage*16384 + SWZQ(row, s0+i), kh + (size_t)row * HD + (s0+i)*8);
            cp16(sb + F_KLO + stage*16384 + SWZQ(row, s0+i), kl + (size_t)row * HD + (s0+i)*8);
        }
        const __nv_bfloat16* vh = g_vthi + (size_t)bh * HD * LL;
        const __nv_bfloat16* vl = g_vtlo + (size_t)bh * HD * LL;
        uint32_t vrow = tid >> 1, vs0 = (tid & 1) * 4;
        #pragma unroll
        for (int i = 0; i < 4; ++i) {
            cp16(sb + F_VHI + stage*16384 + SWZV(vrow, vs0+i), vh + (size_t)vrow*LL + t*64 + (vs0+i)*8);
            cp16(sb + F_VLO + stage*16384 + SWZV(vrow, vs0+i), vl + (size_t)vrow*LL + t*64 + (vs0+i)*8);
        }
    }
    CP_COMMIT();

    float oa[2][4][4];
    #pragma unroll
    for (int mi = 0; mi < 2; ++mi)
        #pragma unroll
        for (int nj = 0; nj < 4; ++nj)
            #pragma unroll
            for (int e = 0; e < 4; ++e) oa[mi][nj][e] = 0.f;

    const int T = LL / 64;
    for (int t = 0; t < T; ++t) {
        const uint32_t cur = (uint32_t)(t & 1) * 16384u;
        CP_WAIT0();
        __syncthreads();

        // ---- S = Q K^T (3-term split) ----
        {
            const uint32_t Khb = sb + F_KHI + cur;
            const uint32_t Klb = sb + F_KLO + cur;
            float sf[2][2][4];
            #pragma unroll
            for (int mi = 0; mi < 2; ++mi)
                #pragma unroll
                for (int nj = 0; nj < 2; ++nj)
                    #pragma unroll
                    for (int e = 0; e < 4; ++e) sf[mi][nj][e] = 0.f;

            #pragma unroll
            for (int ksi = 0; ksi < 8; ++ksi) {
                uint32_t aseg = ksi * 2 + (lane >> 4);
                uint32_t ah[2][4], al_[2][4];
                #pragma unroll
                for (int mi = 0; mi < 2; ++mi) {
                    uint32_t ar = wm * 32 + mi * 16 + (lane & 15);
                    ldmat4(ah[mi],  sb + F_QHI + SWZQ(ar, aseg));
                    ldmat4(al_[mi], sb + F_QLO + SWZQ(ar, aseg));
                }
                uint32_t br = wn * 16 + ((lane >> 4) << 3) + (lane & 7);
                uint32_t bseg = ksi * 2 + ((lane >> 3) & 1);
                uint32_t rb[4], bh2[2][2], bl2[2][2];
                ldmat4(rb, Khb + SWZQ(br, bseg));
                bh2[0][0]=rb[0]; bh2[0][1]=rb[1]; bh2[1][0]=rb[2]; bh2[1][1]=rb[3];
                ldmat4(rb, Klb + SWZQ(br, bseg));
                bl2[0][0]=rb[0]; bl2[0][1]=rb[1]; bl2[1][0]=rb[2]; bl2[1][1]=rb[3];
                #pragma unroll
                for (int mi = 0; mi < 2; ++mi)
                    #pragma unroll
                    for (int nj = 0; nj < 2; ++nj) {
                        mma16816(sf[mi][nj], ah[mi],  bh2[nj], sf[mi][nj]);
                        mma16816(sf[mi][nj], al_[mi], bh2[nj], sf[mi][nj]);
                        mma16816(sf[mi][nj], ah[mi],  bl2[nj], sf[mi][nj]);
                    }
            }
            // store S frags to smem (fp32, stride 68)
            #pragma unroll
            for (int mi = 0; mi < 2; ++mi) {
                int r = wm * 32 + mi * 16 + (lane >> 2);
                #pragma unroll
                for (int nj = 0; nj < 2; ++nj) {
                    int c = wn * 16 + nj * 8 + 2 * (lane & 3);
                    *(float2*)&s_S[r * 68 + c]       = make_float2(sf[mi][nj][0], sf[mi][nj][1]);
                    *(float2*)&s_S[(r + 8) * 68 + c] = make_float2(sf[mi][nj][2], sf[mi][nj][3]);
                }
            }
        }

        // ---- issue KV loads for t+1 (other stage) ----
        if (t + 1 < T) {
            const uint32_t stg = (uint32_t)((t + 1) & 1) * 16384u;
            const int tn = t + 1;
            const __nv_bfloat16* kh = g_khi + ((size_t)bh * LL + (size_t)tn * 64) * HD;
            const __nv_bfloat16* kl = g_klo + ((size_t)bh * LL + (size_t)tn * 64) * HD;
            uint32_t row = tid >> 2, s0 = (tid & 3) * 4;
            #pragma unroll
            for (int i = 0; i < 4; ++i) {
                cp16(sb + F_KHI + stg + SWZQ(row, s0+i), kh + (size_t)row * HD + (s0+i)*8);
                cp16(sb + F_KLO + stg + SWZQ(row, s0+i), kl + (size_t)row * HD + (s0+i)*8);
            }
            const __nv_bfloat16* vh = g_vthi + (size_t)bh * HD * LL;
            const __nv_bfloat16* vl = g_vtlo + (size_t)bh * HD * LL;
            uint32_t vrow = tid >> 1, vs0 = (tid & 1) * 4;
            #pragma unroll
            for (int i = 0; i < 4; ++i) {
                cp16(sb + F_VHI + stg + SWZV(vrow, vs0+i), vh + (size_t)vrow*LL + tn*64 + (vs0+i)*8);
                cp16(sb + F_VLO + stg + SWZV(vrow, vs0+i), vl + (size_t)vrow*LL + tn*64 + (vs0+i)*8);
            }
            CP_COMMIT();
        }
        __syncthreads();

        // ---- online softmax: 4 lanes per row, 16 cols each ----
        {
            int r = tid >> 2, c0 = (tid & 3) * 16;
            float v[16];
            #pragma unroll
            for (int q = 0; q < 4; ++q) {
                float4 f = *(float4*)&s_S[r * 68 + c0 + q * 4];
                v[q*4+0] = f.x * scale; v[q*4+1] = f.y * scale;
                v[q*4+2] = f.z * scale; v[q*4+3] = f.w * scale;
            }
            float mx = v[0];
            #pragma unroll
            for (int j = 1; j < 16; ++j) mx = fmaxf(mx, v[j]);
            mx = fmaxf(mx, __shfl_xor_sync(0xffffffffu, mx, 1));
            mx = fmaxf(mx, __shfl_xor_sync(0xffffffffu, mx, 2));
            float mold = s_mr[r];
            float mnew = fmaxf(mold, mx);
            float alpha = __expf(mold - mnew);
            float p[16], lo[16], sum = 0.f;
            #pragma unroll
            for (int j = 0; j < 16; ++j) { p[j] = __expf(v[j] - mnew); sum += p[j]; }
            sum += __shfl_xor_sync(0xffffffffu, sum, 1);
            sum += __shfl_xor_sync(0xffffffffu, sum, 2);
            __syncwarp();
            if ((tid & 3) == 0) {
                s_mr[r] = mnew;
                s_lr[r] = s_lr[r] * alpha + sum;
                s_al[r] = alpha;
            }
            #pragma unroll
            for (int j = 0; j < 16; ++j) {
                float ph = __bfloat162float(__float2bfloat16(p[j]));
                lo[j] = p[j] - ph;
            }
            uint32_t seg = (uint32_t)(tid & 3) * 2;
            uint4 u;
            u.x = pack2(p[0],p[1]);  u.y = pack2(p[2],p[3]);
            u.z = pack2(p[4],p[5]);  u.w = pack2(p[6],p[7]);
            *(uint4*)(sm + F_PHI + SWZV((uint32_t)r, seg)) = u;
            u.x = pack2(p[8],p[9]);  u.y = pack2(p[10],p[11]);
            u.z = pack2(p[12],p[13]); u.w = pack2(p[14],p[15]);
            *(uint4*)(sm + F_PHI + SWZV((uint32_t)r, seg + 1)) = u;
            u.x = pack2(lo[0],lo[1]); u.y = pack2(lo[2],lo[3]);
            u.z = pack2(lo[4],lo[5]); u.w = pack2(lo[6],lo[7]);
            *(uint4*)(sm + F_PLO + SWZV((uint32_t)r, seg)) = u;
            u.x = pack2(lo[8],lo[9]); u.y = pack2(lo[10],lo[11]);
            u.z = pack2(lo[12],lo[13]); u.w = pack2(lo[14],lo[15]);
            *(uint4*)(sm + F_PLO + SWZV((uint32_t)r, seg + 1)) = u;
        }
        __syncthreads();

        // ---- O = alpha*O + P V (3-term split); warps 2m x 4d ----
        {
            float aR[2][2];
            #pragma unroll
            for (int mi = 0; mi < 2; ++mi) {
                int r = wm * 32 + mi * 16 + (lane >> 2);
                aR[mi][0] = s_al[r];
                aR[mi][1] = s_al[r + 8];
            }
            #pragma unroll
            for (int mi = 0; mi < 2; ++mi)
                #pragma unroll
                for (int nj = 0; nj < 4; ++nj) {
                    oa[mi][nj][0] *= aR[mi][0]; oa[mi][nj][1] *= aR[mi][0];
                    oa[mi][nj][2] *= aR[mi][1]; oa[mi][nj][3] *= aR[mi][1];
                }
            const uint32_t Vhb = sb + F_VHI + cur;
            const uint32_t Vlb = sb + F_VLO + cur;
            #pragma unroll
            for (int ksi = 0; ksi < 4; ++ksi) {
                uint32_t aseg = ksi * 2 + (lane >> 4);
                uint32_t ph[2][4], pl[2][4];
                #pragma unroll
                for (int mi = 0; mi < 2; ++mi) {
                    uint32_t ar = wm * 32 + mi * 16 + (lane & 15);
                    ldmat4(ph[mi], sb + F_PHI + SWZV(ar, aseg));
                    ldmat4(pl[mi], sb + F_PLO + SWZV(ar, aseg));
                }
                uint32_t bh2[4][2], bl2[4][2];
                #pragma unroll
                for (int njp = 0; njp < 2; ++njp) {
                    uint32_t br = wn * 32 + njp * 16 + ((lane >> 4) << 3) + (lane & 7);
                    uint32_t bseg = ksi * 2 + ((lane >> 3) & 1);
                    uint32_t rb[4];
                    ldmat4(rb, Vhb + SWZV(br, bseg));
                    bh2[njp*2][0]=rb[0]; bh2[njp*2][1]=rb[1];
                    bh2[njp*2+1][0]=rb[2]; bh2[njp*2+1][1]=rb[3];
                    ldmat4(rb, Vlb + SWZV(br, bseg));
                    bl2[njp*2][0]=rb[0]; bl2[njp*2][1]=rb[1];
                    bl2[njp*2+1][0]=rb[2]; bl2[njp*2+1][1]=rb[3];
                }
                #pragma unroll
                for (int mi = 0; mi < 2; ++mi)
                    #pragma unroll
                    for (int nj = 0; nj < 4; ++nj) {
                        mma16816(oa[mi][nj], ph[mi], bh2[nj], oa[mi][nj]);
                        mma16816(oa[mi][nj], pl[mi], bh2[nj], oa[mi][nj]);
                        mma16816(oa[mi][nj], ph[mi], bl2[nj], oa[mi][nj]);
                    }
            }
        }
    }

    // ---- write O as bf16 hi/lo into [B, L, DIM] ----
    __syncthreads();
    {
        const int b = bh / HEADS, h = bh % HEADS;
        #pragma unroll
        for (int mi = 0; mi < 2; ++mi) {
            int rloc = wm * 32 + mi * 16 + (lane >> 2);
            float inv0 = 1.f / s_lr[rloc];
            float inv1 = 1.f / s_lr[rloc + 8];
            size_t grow0 = (size_t)(b * LL + qt * 64 + rloc) * DIM;
            size_t grow1 = grow0 + (size_t)8 * DIM;
            #pragma unroll
            for (int nj = 0; nj < 4; ++nj) {
                int col = h * HD + wn * 32 + nj * 8 + 2 * (lane & 3);
                float o0 = oa[mi][nj][0] * inv0, o1 = oa[mi][nj][1] * inv0;
                float o2 = oa[mi][nj][2] * inv1, o3 = oa[mi][nj][3] * inv1;
                float h0 = __bfloat162float(__float2bfloat16(o0));
                float h1 = __bfloat162float(__float2bfloat16(o1));
                float h2 = __bfloat162float(__float2bfloat16(o2));
                float h3 = __bfloat162float(__float2bfloat16(o3));
                *(uint32_t*)&g_ahi[grow0 + col] = pack2(o0, o1);
                *(uint32_t*)&g_alo[grow0 + col] = pack2(o0 - h0, o1 - h1);
                *(uint32_t*)&g_ahi[grow1 + col] = pack2(o2, o3);
                *(uint32_t*)&g_alo[grow1 + col] = pack2(o2 - h2, o3 - h3);
            }
        }
    }
}

// =====================================================================
// launch
// =====================================================================
extern "C" void kernel_launch(void* const* d_in, const int* in_sizes, int n_in,
                              void* d_out, int out_size)
{
    const float* x      = (const float*)d_in[0];
    const float* pe     = (const float*)d_in[1];
    const float* Wqkv   = (const float*)d_in[2];
    const float* bqkv   = (const float*)d_in[3];
    const float* qscale = (const float*)d_in[4];
    const float* kscale = (const float*)d_in[5];
    const float* Wproj  = (const float*)d_in[6];
    const float* bproj  = (const float*)d_in[7];
    float* out = (float*)d_out;

    float* qkv_p;
    cudaGetSymbolAddress((void**)&qkv_p, g_qkv);
    __nv_bfloat16 *xhi, *xlo, *wqhi, *wqlo, *wphi, *wplo, *ahi, *alo;
    cudaGetSymbolAddress((void**)&xhi,  g_xhi);
    cudaGetSymbolAddress((void**)&xlo,  g_xlo);
    cudaGetSymbolAddress((void**)&wqhi, g_wqhi);
    cudaGetSymbolAddress((void**)&wqlo, g_wqlo);
    cudaGetSymbolAddress((void**)&wphi, g_wphi);
    cudaGetSymbolAddress((void**)&wplo, g_wplo);
    cudaGetSymbolAddress((void**)&ahi,  g_ahi);
    cudaGetSymbolAddress((void**)&alo,  g_alo);

    const size_t smem_gemm = 2 * (size_t)STAGE_B;   // 64 KB
    cudaFuncSetAttribute(gemm_split, cudaFuncAttributeMaxDynamicSharedMemorySize,
                         (int)smem_gemm);
    cudaFuncSetAttribute(flash_attn_mma, cudaFuncAttributeMaxDynamicSharedMemorySize,
                         F_TOT);

    // 0) bf16 splits of inputs
    split_bf16<<<2048, 256>>>(x,     xhi,  xlo,  (size_t)MTOT * DIM);
    split_bf16<<<2048, 256>>>(Wqkv,  wqhi, wqlo, (size_t)NQKV * DIM);
    split_bf16<<<2048, 256>>>(Wproj, wphi, wplo, (size_t)DIM * DIM);

    // 1) QKV GEMM (mma.sync)
    gemm_split<<<dim3(NQKV/128, MTOT/128), 256, smem_gemm>>>(
        xhi, xlo, wqhi, wqlo, bqkv, qkv_p, NQKV, DIM);

    // 2) RMSNorm + RoPE + transpose + bf16 hi/lo
    qkv_post<<<BB*LL*HEADS, 128>>>(pe, qscale, kscale);

    // 3) tensor-core flash attention -> g_ahi/g_alo directly
    flash_attn_mma<<<dim3(LL/64, BH), 256, F_TOT>>>();

    // 4) proj GEMM (mma.sync)
    gemm_split<<<dim3(DIM/128, MTOT/128), 256, smem_gemm>>>(
        ahi, alo, wphi, wplo, bproj, out, DIM, DIM);
}

// round 6
// speedup vs baseline: 2.8663x; 1.4065x over previous
#include <cuda_runtime.h>
#include <cuda_bf16.h>
#include <cuda_fp16.h>
#include <cstdint>
#include <math.h>

#define DIM   3072
#define HEADS 24
#define HD    128
#define BB    2
#define LL    2048
#define MTOT  (BB*LL)          // 4096 rows
#define NQKV  (3*DIM)          // 9216
#define BH    (BB*HEADS)       // 48

// ---------------- scratch (static device globals; no runtime alloc) ----------------
__device__ float g_qkv[(size_t)MTOT * NQKV];        // [B*L, 3*DIM]

__device__ __half g_xhi [(size_t)MTOT * DIM];       // x split (fp16 hi/lo)
__device__ __half g_xlo [(size_t)MTOT * DIM];
__device__ __half g_wq16[(size_t)NQKV * DIM];       // Wqkv single fp16
__device__ __half g_wp16[(size_t)DIM * DIM];        // Wproj single fp16
__device__ __half g_ahi [(size_t)MTOT * DIM];       // attention out split
__device__ __half g_alo [(size_t)MTOT * DIM];

__device__ __nv_bfloat16 g_qhi [(size_t)BH*LL*HD];  // [BH, L, D] (flash, bf16 3-term)
__device__ __nv_bfloat16 g_qlo [(size_t)BH*LL*HD];
__device__ __nv_bfloat16 g_khi [(size_t)BH*LL*HD];
__device__ __nv_bfloat16 g_klo [(size_t)BH*LL*HD];
__device__ __nv_bfloat16 g_vthi[(size_t)BH*HD*LL];  // [BH, D, L] (transposed)
__device__ __nv_bfloat16 g_vtlo[(size_t)BH*HD*LL];

// ====================== helpers ======================
__device__ __forceinline__ uint32_t smem_to_u32(const void* p) {
    uint32_t a;
    asm("{ .reg .u64 t; cvta.to.shared.u64 t, %1; cvt.u32.u64 %0, t; }" : "=r"(a) : "l"(p));
    return a;
}
__device__ __forceinline__ void cp16(uint32_t s, const void* g) {
    asm volatile("cp.async.cg.shared.global [%0], [%1], 16;\n" :: "r"(s), "l"(g));
}
#define CP_COMMIT() asm volatile("cp.async.commit_group;\n" ::: "memory")
#define CP_WAIT1()  asm volatile("cp.async.wait_group 1;\n" ::: "memory")
#define CP_WAIT0()  asm volatile("cp.async.wait_group 0;\n" ::: "memory")

__device__ __forceinline__ void ldmat4(uint32_t* r, uint32_t addr) {
    asm volatile("ldmatrix.sync.aligned.m8n8.x4.shared.b16 {%0,%1,%2,%3}, [%4];"
                 : "=r"(r[0]), "=r"(r[1]), "=r"(r[2]), "=r"(r[3]) : "r"(addr));
}
__device__ __forceinline__ void mma16816(float* d, const uint32_t* a,
                                         const uint32_t* b, const float* c) {
    asm volatile("mma.sync.aligned.m16n8k16.row.col.f32.bf16.bf16.f32 "
                 "{%0,%1,%2,%3}, {%4,%5,%6,%7}, {%8,%9}, {%10,%11,%12,%13};"
                 : "=f"(d[0]), "=f"(d[1]), "=f"(d[2]), "=f"(d[3])
                 : "r"(a[0]), "r"(a[1]), "r"(a[2]), "r"(a[3]),
                   "r"(b[0]), "r"(b[1]),
                   "f"(c[0]), "f"(c[1]), "f"(c[2]), "f"(c[3]));
}
__device__ __forceinline__ void mma16816h(float* d, const uint32_t* a,
                                          const uint32_t* b, const float* c) {
    asm volatile("mma.sync.aligned.m16n8k16.row.col.f32.f16.f16.f32 "
                 "{%0,%1,%2,%3}, {%4,%5,%6,%7}, {%8,%9}, {%10,%11,%12,%13};"
                 : "=f"(d[0]), "=f"(d[1]), "=f"(d[2]), "=f"(d[3])
                 : "r"(a[0]), "r"(a[1]), "r"(a[2]), "r"(a[3]),
                   "r"(b[0]), "r"(b[1]),
                   "f"(c[0]), "f"(c[1]), "f"(c[2]), "f"(c[3]));
}
__device__ __forceinline__ uint32_t pack2(float a, float b) {
    __nv_bfloat16 x = __float2bfloat16(a), y = __float2bfloat16(b);
    uint16_t ux = *(uint16_t*)&x, uy = *(uint16_t*)&y;
    return (uint32_t)ux | ((uint32_t)uy << 16);
}
__device__ __forceinline__ uint32_t pack2h(float a, float b) {
    __half2 h = __floats2half2_rn(a, b);
    return *(uint32_t*)&h;
}

// =====================================================================
// conversion kernels
// =====================================================================
__global__ __launch_bounds__(256) void split_f16(
    const float* __restrict__ in, __half* __restrict__ hi,
    __half* __restrict__ lo, size_t n)
{
    for (size_t i = (size_t)blockIdx.x * blockDim.x + threadIdx.x; i < n;
         i += (size_t)gridDim.x * blockDim.x) {
        float v = in[i];
        __half h = __float2half_rn(v);
        hi[i] = h;
        lo[i] = __float2half_rn(v - __half2float(h));
    }
}
__global__ __launch_bounds__(256) void conv_f16(
    const float* __restrict__ in, __half* __restrict__ out, size_t n)
{
    for (size_t i = (size_t)blockIdx.x * blockDim.x + threadIdx.x; i < n;
         i += (size_t)gridDim.x * blockDim.x)
        out[i] = __float2half_rn(in[i]);
}

// =====================================================================
// fp16 2-term GEMM: C[M,N] = (Ahi+Alo)[M,K] @ B16[N,K]^T + bias
// CTA 128x128, 8 warps (2m x 4n), BK=32, 3-stage cp.async, 2 CTA/SM.
// =====================================================================
#define BK 32
#define TILE_B 8192            // 128 rows * 64 bytes (32 halves)
#define STAGE3 (3*TILE_B)      // Ahi, Alo, B

__device__ __forceinline__ uint32_t swz(uint32_t row, uint32_t seg) {
    return row * 64u + ((seg ^ (row & 3u)) * 16u);
}

__global__ __launch_bounds__(256, 2) void gemm_f16(
    const __half* __restrict__ Ahi, const __half* __restrict__ Alo,
    const __half* __restrict__ B16,
    const float* __restrict__ bias, float* __restrict__ C, int N, int K)
{
    extern __shared__ __align__(128) char smem[];
    const uint32_t sb = smem_to_u32(smem);
    const int tid = threadIdx.x;
    const int wid = tid >> 5, lane = tid & 31;
    const int wm = wid & 1, wn = wid >> 1;
    const int bm = blockIdx.y * 128, bn = blockIdx.x * 128;

    const __half* src[3] = { Ahi + (size_t)bm * K, Alo + (size_t)bm * K,
                             B16 + (size_t)bn * K };

    const uint32_t seg0 = (uint32_t)tid * 2;
    const uint32_t r0 = seg0 >> 2, ks0 = seg0 & 3;

    // prologue: stages 0,1
    #pragma unroll
    for (int s = 0; s < 2; ++s) {
        const int k0 = s * BK;
        #pragma unroll
        for (int t = 0; t < 3; ++t) {
            uint32_t dst = sb + (uint32_t)s * STAGE3 + (uint32_t)t * TILE_B;
            const __half* g = src[t] + (size_t)r0 * K + k0;
            cp16(dst + swz(r0, ks0),     g + ks0 * 8);
            cp16(dst + swz(r0, ks0 + 1), g + ks0 * 8 + 8);
        }
        CP_COMMIT();
    }

    float acc[4][4][4];
    #pragma unroll
    for (int i = 0; i < 4; ++i)
        #pragma unroll
        for (int j = 0; j < 4; ++j)
            #pragma unroll
            for (int e = 0; e < 4; ++e) acc[i][j][e] = 0.f;

    const uint32_t a_row = (uint32_t)(wm * 64 + (lane & 15));
    const uint32_t a_seg = (uint32_t)(lane >> 4);
    const uint32_t b_row = (uint32_t)(wn * 32 + ((lane >> 4) << 3) + (lane & 7));
    const uint32_t b_seg = (uint32_t)((lane >> 3) & 1);

    const int nchunk = K / BK;   // 96
    int slot = 0;                // slot = t % 3
    for (int t = 0; t < nchunk; ++t) {
        if (t + 1 < nchunk) CP_WAIT1(); else CP_WAIT0();
        __syncthreads();

        // prefetch stage t+2 into slot (t+2)%3  (freed by compute of t-1)
        if (t + 2 < nchunk) {
            int ps = slot + 2; if (ps >= 3) ps -= 3;
            const int k0 = (t + 2) * BK;
            #pragma unroll
            for (int tt = 0; tt < 3; ++tt) {
                uint32_t dst = sb + (uint32_t)ps * STAGE3 + (uint32_t)tt * TILE_B;
                const __half* g = src[tt] + (size_t)r0 * K + k0;
                cp16(dst + swz(r0, ks0),     g + ks0 * 8);
                cp16(dst + swz(r0, ks0 + 1), g + ks0 * 8 + 8);
            }
            CP_COMMIT();
        }

        const uint32_t Ah = sb + (uint32_t)slot * STAGE3;
        const uint32_t Al = Ah + TILE_B;
        const uint32_t Bt = Al + TILE_B;

        #pragma unroll
        for (int ks = 0; ks < 2; ++ks) {
            uint32_t ah[4][4], al[4][4], bh[4][2];
            #pragma unroll
            for (int mi = 0; mi < 4; ++mi) {
                uint32_t row = a_row + mi * 16;
                uint32_t seg = a_seg + ks * 2;
                ldmat4(ah[mi], Ah + swz(row, seg));
                ldmat4(al[mi], Al + swz(row, seg));
            }
            #pragma unroll
            for (int njp = 0; njp < 2; ++njp) {
                uint32_t row = b_row + njp * 16;
                uint32_t seg = b_seg + ks * 2;
                uint32_t rb[4];
                ldmat4(rb, Bt + swz(row, seg));
                bh[njp*2][0] = rb[0]; bh[njp*2][1] = rb[1];
                bh[njp*2+1][0] = rb[2]; bh[njp*2+1][1] = rb[3];
            }
            #pragma unroll
            for (int mi = 0; mi < 4; ++mi)
                #pragma unroll
                for (int nj = 0; nj < 4; ++nj) {
                    mma16816h(acc[mi][nj], ah[mi], bh[nj], acc[mi][nj]);
                    mma16816h(acc[mi][nj], al[mi], bh[nj], acc[mi][nj]);
                }
        }
        ++slot; if (slot >= 3) slot = 0;
    }

    const int g = lane >> 2, tc = lane & 3;
    #pragma unroll
    for (int mi = 0; mi < 4; ++mi) {
        int row = bm + wm * 64 + mi * 16 + g;
        #pragma unroll
        for (int nj = 0; nj < 4; ++nj) {
            int col = bn + wn * 32 + nj * 8 + tc * 2;
            float b0 = bias[col], b1 = bias[col + 1];
            float2 v0 = make_float2(acc[mi][nj][0] + b0, acc[mi][nj][1] + b1);
            float2 v1 = make_float2(acc[mi][nj][2] + b0, acc[mi][nj][3] + b1);
            *(float2*)(C + (size_t)row * N + col) = v0;
            *(float2*)(C + (size_t)(row + 8) * N + col) = v1;
        }
    }
}

// =====================================================================
// RMSNorm(q,k) + RoPE; q,k bf16 hi/lo [BH,L,D]; v transposed [BH,D,L].
// =====================================================================
__global__ __launch_bounds__(128) void qkv_post(
    const float* __restrict__ pe, const float* __restrict__ qscale,
    const float* __restrict__ kscale)
{
    __shared__ float sq[128], sk[128], qs[128], ks[128];
    const int idx = blockIdx.x;
    const int h = idx % HEADS;
    const int l = (idx / HEADS) % LL;
    const int b = idx / (HEADS * LL);
    const int d = threadIdx.x;

    const size_t row = (size_t)(b * LL + l) * NQKV;
    float qv = g_qkv[row +           h*HD + d];
    float kv = g_qkv[row + DIM     + h*HD + d];
    float vv = g_qkv[row + 2*DIM   + h*HD + d];

    sq[d] = qv * qv; sk[d] = kv * kv;
    __syncthreads();
    for (int off = 64; off > 0; off >>= 1) {
        if (d < off) { sq[d] += sq[d+off]; sk[d] += sk[d+off]; }
        __syncthreads();
    }
    float rq = rsqrtf(sq[0] * (1.f/HD) + 1e-6f);
    float rk = rsqrtf(sk[0] * (1.f/HD) + 1e-6f);
    qs[d] = qv * rq * qscale[d];
    ks[d] = kv * rk * kscale[d];
    __syncthreads();

    const int p = d >> 1, r = d & 1;
    const float* pe4 = pe + (((size_t)l * 64 + p) * 2 + r) * 2;
    float qo = pe4[0]*qs[2*p] + pe4[1]*qs[2*p+1];
    float ko = pe4[0]*ks[2*p] + pe4[1]*ks[2*p+1];

    const int bh = b * HEADS + h;
    const size_t qk = ((size_t)bh * LL + l) * HD + d;
    __nv_bfloat16 qh = __float2bfloat16(qo);
    g_qhi[qk] = qh;  g_qlo[qk] = __float2bfloat16(qo - __bfloat162float(qh));
    __nv_bfloat16 kh = __float2bfloat16(ko);
    g_khi[qk] = kh;  g_klo[qk] = __float2bfloat16(ko - __bfloat162float(kh));
    const size_t vt = ((size_t)bh * HD + d) * LL + l;
    __nv_bfloat16 vh = __float2bfloat16(vv);
    g_vthi[vt] = vh; g_vtlo[vt] = __float2bfloat16(vv - __bfloat162float(vh));
}

// =====================================================================
// tensor-core flash attention (bf16 hi/lo split, online softmax)
// BM=64, BN=64, D=128, 8 warps.  (validated round 5)
// =====================================================================
#define SWZQ(r, s) ((r)*256u + ((uint32_t)((s) ^ ((r) & 7u)) * 16u))   // 256B rows
#define SWZV(r, s) ((r)*128u + ((uint32_t)((s) ^ ((r) & 7u)) * 16u))   // 128B rows

#define F_QHI 0
#define F_QLO 16384
#define F_KHI 32768      // 2 stages x 16384
#define F_KLO 65536
#define F_VHI 98304
#define F_VLO 131072
#define F_SS  163840     // fp32 [64][68] = 17408
#define F_PHI 181248
#define F_PLO 189440
#define F_MR  197632
#define F_LR  197888
#define F_AL  198144
#define F_TOT 198400

__global__ __launch_bounds__(256, 1) void flash_attn_mma()
{
    extern __shared__ __align__(128) char sm[];
    const uint32_t sb = smem_to_u32(sm);
    float* s_S  = (float*)(sm + F_SS);
    float* s_mr = (float*)(sm + F_MR);
    float* s_lr = (float*)(sm + F_LR);
    float* s_al = (float*)(sm + F_AL);

    const int tid = threadIdx.x, lane = tid & 31, wid = tid >> 5;
    const int wm = wid & 1, wn = wid >> 1;
    const int bh = blockIdx.y, qt = blockIdx.x;
    const float scale = 0.08838834764831845f;

    if (tid < 64) { s_mr[tid] = -INFINITY; s_lr[tid] = 0.f; }

    {
        const __nv_bfloat16* qh = g_qhi + ((size_t)bh * LL + (size_t)qt * 64) * HD;
        const __nv_bfloat16* ql = g_qlo + ((size_t)bh * LL + (size_t)qt * 64) * HD;
        uint32_t row = tid >> 2, s0 = (tid & 3) * 4;
        #pragma unroll
        for (int i = 0; i < 4; ++i) {
            cp16(sb + F_QHI + SWZQ(row, s0 + i), qh + (size_t)row * HD + (s0 + i) * 8);
            cp16(sb + F_QLO + SWZQ(row, s0 + i), ql + (size_t)row * HD + (s0 + i) * 8);
        }
    }
    {
        const int t = 0, stage = 0;
        const __nv_bfloat16* kh = g_khi + ((size_t)bh * LL + (size_t)t * 64) * HD;
        const __nv_bfloat16* kl = g_klo + ((size_t)bh * LL + (size_t)t * 64) * HD;
        uint32_t row = tid >> 2, s0 = (tid & 3) * 4;
        #pragma unroll
        for (int i = 0; i < 4; ++i) {
            cp16(sb + F_KHI + stage*16384 + SWZQ(row, s0+i), kh + (size_t)row * HD + (s0+i)*8);
            cp16(sb + F_KLO + stage*16384 + SWZQ(row, s0+i), kl + (size_t)row * HD + (s0+i)*8);
        }
        const __nv_bfloat16* vh = g_vthi + (size_t)bh * HD * LL;
        const __nv_bfloat16* vl = g_vtlo + (size_t)bh * HD * LL;
        uint32_t vrow = tid >> 1, vs0 = (tid & 1) * 4;
        #pragma unroll
        for (int i = 0; i < 4; ++i) {
            cp16(sb + F_VHI + stage*16384 + SWZV(vrow, vs0+i), vh + (size_t)vrow*LL + t*64 + (vs0+i)*8);
            cp16(sb + F_VLO + stage*16384 + SWZV(vrow, vs0+i), vl + (size_t)vrow*LL + t*64 + (vs0+i)*8);
        }
    }
    CP_COMMIT();

    float oa[2][4][4];
    #pragma unroll
    for (int mi = 0; mi < 2; ++mi)
        #pragma unroll
        for (int nj = 0; nj < 4; ++nj)
            #pragma unroll
            for (int e = 0; e < 4; ++e) oa[mi][nj][e] = 0.f;

    const int T = LL / 64;
    for (int t = 0; t < T; ++t) {
        const uint32_t cur = (uint32_t)(t & 1) * 16384u;
        CP_WAIT0();
        __syncthreads();

        // ---- S = Q K^T (3-term split) ----
        {
            const uint32_t Khb = sb + F_KHI + cur;
            const uint32_t Klb = sb + F_KLO + cur;
            float sf[2][2][4];
            #pragma unroll
            for (int mi = 0; mi < 2; ++mi)
                #pragma unroll
                for (int nj = 0; nj < 2; ++nj)
                    #pragma unroll
                    for (int e = 0; e < 4; ++e) sf[mi][nj][e] = 0.f;

            #pragma unroll
            for (int ksi = 0; ksi < 8; ++ksi) {
                uint32_t aseg = ksi * 2 + (lane >> 4);
                uint32_t ah[2][4], al_[2][4];
                #pragma unroll
                for (int mi = 0; mi < 2; ++mi) {
                    uint32_t ar = wm * 32 + mi * 16 + (lane & 15);
                    ldmat4(ah[mi],  sb + F_QHI + SWZQ(ar, aseg));
                    ldmat4(al_[mi], sb + F_QLO + SWZQ(ar, aseg));
                }
                uint32_t br = wn * 16 + ((lane >> 4) << 3) + (lane & 7);
                uint32_t bseg = ksi * 2 + ((lane >> 3) & 1);
                uint32_t rb[4], bh2[2][2], bl2[2][2];
                ldmat4(rb, Khb + SWZQ(br, bseg));
                bh2[0][0]=rb[0]; bh2[0][1]=rb[1]; bh2[1][0]=rb[2]; bh2[1][1]=rb[3];
                ldmat4(rb, Klb + SWZQ(br, bseg));
                bl2[0][0]=rb[0]; bl2[0][1]=rb[1]; bl2[1][0]=rb[2]; bl2[1][1]=rb[3];
                #pragma unroll
                for (int mi = 0; mi < 2; ++mi)
                    #pragma unroll
                    for (int nj = 0; nj < 2; ++nj) {
                        mma16816(sf[mi][nj], ah[mi],  bh2[nj], sf[mi][nj]);
                        mma16816(sf[mi][nj], al_[mi], bh2[nj], sf[mi][nj]);
                        mma16816(sf[mi][nj], ah[mi],  bl2[nj], sf[mi][nj]);
                    }
            }
            #pragma unroll
            for (int mi = 0; mi < 2; ++mi) {
                int r = wm * 32 + mi * 16 + (lane >> 2);
                #pragma unroll
                for (int nj = 0; nj < 2; ++nj) {
                    int c = wn * 16 + nj * 8 + 2 * (lane & 3);
                    *(float2*)&s_S[r * 68 + c]       = make_float2(sf[mi][nj][0], sf[mi][nj][1]);
                    *(float2*)&s_S[(r + 8) * 68 + c] = make_float2(sf[mi][nj][2], sf[mi][nj][3]);
                }
            }
        }

        if (t + 1 < T) {
            const uint32_t stg = (uint32_t)((t + 1) & 1) * 16384u;
            const int tn = t + 1;
            const __nv_bfloat16* kh = g_khi + ((size_t)bh * LL + (size_t)tn * 64) * HD;
            const __nv_bfloat16* kl = g_klo + ((size_t)bh * LL + (size_t)tn * 64) * HD;
            uint32_t row = tid >> 2, s0 = (tid & 3) * 4;
            #pragma unroll
            for (int i = 0; i < 4; ++i) {
                cp16(sb + F_KHI + stg + SWZQ(row, s0+i), kh + (size_t)row * HD + (s0+i)*8);
                cp16(sb + F_KLO + stg + SWZQ(row, s0+i), kl + (size_t)row * HD + (s0+i)*8);
            }
            const __nv_bfloat16* vh = g_vthi + (size_t)bh * HD * LL;
            const __nv_bfloat16* vl = g_vtlo + (size_t)bh * HD * LL;
            uint32_t vrow = tid >> 1, vs0 = (tid & 1) * 4;
            #pragma unroll
            for (int i = 0; i < 4; ++i) {
                cp16(sb + F_VHI + stg + SWZV(vrow, vs0+i), vh + (size_t)vrow*LL + tn*64 + (vs0+i)*8);
                cp16(sb + F_VLO + stg + SWZV(vrow, vs0+i), vl + (size_t)vrow*LL + tn*64 + (vs0+i)*8);
            }
            CP_COMMIT();
        }
        __syncthreads();

        // ---- online softmax ----
        {
            int r = tid >> 2, c0 = (tid & 3) * 16;
            float v[16];
            #pragma unroll
            for (int q = 0; q < 4; ++q) {
                float4 f = *(float4*)&s_S[r * 68 + c0 + q * 4];
                v[q*4+0] = f.x * scale; v[q*4+1] = f.y * scale;
                v[q*4+2] = f.z * scale; v[q*4+3] = f.w * scale;
            }
            float mx = v[0];
            #pragma unroll
            for (int j = 1; j < 16; ++j) mx = fmaxf(mx, v[j]);
            mx = fmaxf(mx, __shfl_xor_sync(0xffffffffu, mx, 1));
            mx = fmaxf(mx, __shfl_xor_sync(0xffffffffu, mx, 2));
            float mold = s_mr[r];
            float mnew = fmaxf(mold, mx);
            float alpha = __expf(mold - mnew);
            float p[16], lo[16], sum = 0.f;
            #pragma unroll
            for (int j = 0; j < 16; ++j) { p[j] = __expf(v[j] - mnew); sum += p[j]; }
            sum += __shfl_xor_sync(0xffffffffu, sum, 1);
            sum += __shfl_xor_sync(0xffffffffu, sum, 2);
            __syncwarp();
            if ((tid & 3) == 0) {
                s_mr[r] = mnew;
                s_lr[r] = s_lr[r] * alpha + sum;
                s_al[r] = alpha;
            }
            #pragma unroll
            for (int j = 0; j < 16; ++j) {
                float ph = __bfloat162float(__float2bfloat16(p[j]));
                lo[j] = p[j] - ph;
            }
            uint32_t seg = (uint32_t)(tid & 3) * 2;
            uint4 u;
            u.x = pack2(p[0],p[1]);  u.y = pack2(p[2],p[3]);
            u.z = pack2(p[4],p[5]);  u.w = pack2(p[6],p[7]);
            *(uint4*)(sm + F_PHI + SWZV((uint32_t)r, seg)) = u;
            u.x = pack2(p[8],p[9]);  u.y = pack2(p[10],p[11]);
            u.z = pack2(p[12],p[13]); u.w = pack2(p[14],p[15]);
            *(uint4*)(sm + F_PHI + SWZV((uint32_t)r, seg + 1)) = u;
            u.x = pack2(lo[0],lo[1]); u.y = pack2(lo[2],lo[3]);
            u.z = pack2(lo[4],lo[5]); u.w = pack2(lo[6],lo[7]);
            *(uint4*)(sm + F_PLO + SWZV((uint32_t)r, seg)) = u;
            u.x = pack2(lo[8],lo[9]); u.y = pack2(lo[10],lo[11]);
            u.z = pack2(lo[12],lo[13]); u.w = pack2(lo[14],lo[15]);
            *(uint4*)(sm + F_PLO + SWZV((uint32_t)r, seg + 1)) = u;
        }
        __syncthreads();

        // ---- O = alpha*O + P V (3-term split) ----
        {
            float aR[2][2];
            #pragma unroll
            for (int mi = 0; mi < 2; ++mi) {
                int r = wm * 32 + mi * 16 + (lane >> 2);
                aR[mi][0] = s_al[r];
                aR[mi][1] = s_al[r + 8];
            }
            #pragma unroll
            for (int mi = 0; mi < 2; ++mi)
                #pragma unroll
                for (int nj = 0; nj < 4; ++nj) {
                    oa[mi][nj][0] *= aR[mi][0]; oa[mi][nj][1] *= aR[mi][0];
                    oa[mi][nj][2] *= aR[mi][1]; oa[mi][nj][3] *= aR[mi][1];
                }
            const uint32_t Vhb = sb + F_VHI + cur;
            const uint32_t Vlb = sb + F_VLO + cur;
            #pragma unroll
            for (int ksi = 0; ksi < 4; ++ksi) {
                uint32_t aseg = ksi * 2 + (lane >> 4);
                uint32_t ph[2][4], pl[2][4];
                #pragma unroll
                for (int mi = 0; mi < 2; ++mi) {
                    uint32_t ar = wm * 32 + mi * 16 + (lane & 15);
                    ldmat4(ph[mi], sb + F_PHI + SWZV(ar, aseg));
                    ldmat4(pl[mi], sb + F_PLO + SWZV(ar, aseg));
                }
                uint32_t bh2[4][2], bl2[4][2];
                #pragma unroll
                for (int njp = 0; njp < 2; ++njp) {
                    uint32_t br = wn * 32 + njp * 16 + ((lane >> 4) << 3) + (lane & 7);
                    uint32_t bseg = ksi * 2 + ((lane >> 3) & 1);
                    uint32_t rb[4];
                    ldmat4(rb, Vhb + SWZV(br, bseg));
                    bh2[njp*2][0]=rb[0]; bh2[njp*2][1]=rb[1];
                    bh2[njp*2+1][0]=rb[2]; bh2[njp*2+1][1]=rb[3];
                    ldmat4(rb, Vlb + SWZV(br, bseg));
                    bl2[njp*2][0]=rb[0]; bl2[njp*2][1]=rb[1];
                    bl2[njp*2+1][0]=rb[2]; bl2[njp*2+1][1]=rb[3];
                }
                #pragma unroll
                for (int mi = 0; mi < 2; ++mi)
                    #pragma unroll
                    for (int nj = 0; nj < 4; ++nj) {
                        mma16816(oa[mi][nj], ph[mi], bh2[nj], oa[mi][nj]);
                        mma16816(oa[mi][nj], pl[mi], bh2[nj], oa[mi][nj]);
                        mma16816(oa[mi][nj], ph[mi], bl2[nj], oa[mi][nj]);
                    }
            }
        }
    }

    // ---- write O as fp16 hi/lo into [B, L, DIM] (proj GEMM input) ----
    __syncthreads();
    {
        const int b = bh / HEADS, h = bh % HEADS;
        #pragma unroll
        for (int mi = 0; mi < 2; ++mi) {
            int rloc = wm * 32 + mi * 16 + (lane >> 2);
            float inv0 = 1.f / s_lr[rloc];
            float inv1 = 1.f / s_lr[rloc + 8];
            size_t grow0 = (size_t)(b * LL + qt * 64 + rloc) * DIM;
            size_t grow1 = grow0 + (size_t)8 * DIM;
            #pragma unroll
            for (int nj = 0; nj < 4; ++nj) {
                int col = h * HD + wn * 32 + nj * 8 + 2 * (lane & 3);
                float o0 = oa[mi][nj][0] * inv0, o1 = oa[mi][nj][1] * inv0;
                float o2 = oa[mi][nj][2] * inv1, o3 = oa[mi][nj][3] * inv1;
                float h0 = __half2float(__float2half_rn(o0));
                float h1 = __half2float(__float2half_rn(o1));
                float h2 = __half2float(__float2half_rn(o2));
                float h3 = __half2float(__float2half_rn(o3));
                *(uint32_t*)&g_ahi[grow0 + col] = pack2h(o0, o1);
                *(uint32_t*)&g_alo[grow0 + col] = pack2h(o0 - h0, o1 - h1);
                *(uint32_t*)&g_ahi[grow1 + col] = pack2h(o2, o3);
                *(uint32_t*)&g_alo[grow1 + col] = pack2h(o2 - h2, o3 - h3);
            }
        }
    }
}

// =====================================================================
// launch
// =====================================================================
extern "C" void kernel_launch(void* const* d_in, const int* in_sizes, int n_in,
                              void* d_out, int out_size)
{
    const float* x      = (const float*)d_in[0];
    const float* pe     = (const float*)d_in[1];
    const float* Wqkv   = (const float*)d_in[2];
    const float* bqkv   = (const float*)d_in[3];
    const float* qscale = (const float*)d_in[4];
    const float* kscale = (const float*)d_in[5];
    const float* Wproj  = (const float*)d_in[6];
    const float* bproj  = (const float*)d_in[7];
    float* out = (float*)d_out;

    float* qkv_p;
    cudaGetSymbolAddress((void**)&qkv_p, g_qkv);
    __half *xhi, *xlo, *wq16, *wp16, *ahi, *alo;
    cudaGetSymbolAddress((void**)&xhi,  g_xhi);
    cudaGetSymbolAddress((void**)&xlo,  g_xlo);
    cudaGetSymbolAddress((void**)&wq16, g_wq16);
    cudaGetSymbolAddress((void**)&wp16, g_wp16);
    cudaGetSymbolAddress((void**)&ahi,  g_ahi);
    cudaGetSymbolAddress((void**)&alo,  g_alo);

    const size_t smem_gemm = 3 * (size_t)STAGE3 / 1;   // 73728 B
    cudaFuncSetAttribute(gemm_f16, cudaFuncAttributeMaxDynamicSharedMemorySize,
                         (int)(3 * STAGE3));
    cudaFuncSetAttribute(flash_attn_mma, cudaFuncAttributeMaxDynamicSharedMemorySize,
                         F_TOT);
    (void)smem_gemm;

    // 0) fp16 conversions
    split_f16<<<2048, 256>>>(x,     xhi,  xlo, (size_t)MTOT * DIM);
    conv_f16 <<<2048, 256>>>(Wqkv,  wq16, (size_t)NQKV * DIM);
    conv_f16 <<<2048, 256>>>(Wproj, wp16, (size_t)DIM * DIM);

    // 1) QKV GEMM (fp16 2-term)
    gemm_f16<<<dim3(NQKV/128, MTOT/128), 256, 3 * STAGE3>>>(
        xhi, xlo, wq16, bqkv, qkv_p, NQKV, DIM);

    // 2) RMSNorm + RoPE + transpose + bf16 hi/lo
    qkv_post<<<BB*LL*HEADS, 128>>>(pe, qscale, kscale);

    // 3) tensor-core flash attention -> g_ahi/g_alo (fp16 hi/lo)
    flash_attn_mma<<<dim3(LL/64, BH), 256, F_TOT>>>();

    // 4) proj GEMM (fp16 2-term)
    gemm_f16<<<dim3(DIM/128, MTOT/128), 256, 3 * STAGE3>>>(
        ahi, alo, wp16, bproj, out, DIM, DIM);
}

// round 7
// speedup vs baseline: 3.9831x; 1.3897x over previous
#include <cuda_runtime.h>
#include <cuda_bf16.h>
#include <cuda_fp16.h>
#include <cstdint>
#include <math.h>

#define DIM   3072
#define HEADS 24
#define HD    128
#define BB    2
#define LL    2048
#define MTOT  (BB*LL)          // 4096 rows
#define NQKV  (3*DIM)          // 9216
#define BH    (BB*HEADS)       // 48

// ---------------- scratch (static device globals; no runtime alloc) ----------------
__device__ float g_qkv[(size_t)MTOT * NQKV];        // [B*L, 3*DIM]

__device__ __half g_x16 [(size_t)MTOT * DIM];       // x fp16
__device__ __half g_wq16[(size_t)NQKV * DIM];       // Wqkv fp16
__device__ __half g_wp16[(size_t)DIM * DIM];        // Wproj fp16
__device__ __half g_a16 [(size_t)MTOT * DIM];       // attention out fp16

__device__ __nv_bfloat16 g_qhi [(size_t)BH*LL*HD];  // [BH, L, D] (flash, bf16 3-term)
__device__ __nv_bfloat16 g_qlo [(size_t)BH*LL*HD];
__device__ __nv_bfloat16 g_khi [(size_t)BH*LL*HD];
__device__ __nv_bfloat16 g_klo [(size_t)BH*LL*HD];
__device__ __nv_bfloat16 g_vthi[(size_t)BH*HD*LL];  // [BH, D, L] (transposed)
__device__ __nv_bfloat16 g_vtlo[(size_t)BH*HD*LL];

// ====================== helpers ======================
__device__ __forceinline__ uint32_t smem_to_u32(const void* p) {
    uint32_t a;
    asm("{ .reg .u64 t; cvta.to.shared.u64 t, %1; cvt.u32.u64 %0, t; }" : "=r"(a) : "l"(p));
    return a;
}
__device__ __forceinline__ void cp16(uint32_t s, const void* g) {
    asm volatile("cp.async.cg.shared.global [%0], [%1], 16;\n" :: "r"(s), "l"(g));
}
#define CP_COMMIT() asm volatile("cp.async.commit_group;\n" ::: "memory")
#define CP_WAIT1()  asm volatile("cp.async.wait_group 1;\n" ::: "memory")
#define CP_WAIT0()  asm volatile("cp.async.wait_group 0;\n" ::: "memory")

__device__ __forceinline__ void ldmat4(uint32_t* r, uint32_t addr) {
    asm volatile("ldmatrix.sync.aligned.m8n8.x4.shared.b16 {%0,%1,%2,%3}, [%4];"
                 : "=r"(r[0]), "=r"(r[1]), "=r"(r[2]), "=r"(r[3]) : "r"(addr));
}
__device__ __forceinline__ void mma16816(float* d, const uint32_t* a,
                                         const uint32_t* b, const float* c) {
    asm volatile("mma.sync.aligned.m16n8k16.row.col.f32.bf16.bf16.f32 "
                 "{%0,%1,%2,%3}, {%4,%5,%6,%7}, {%8,%9}, {%10,%11,%12,%13};"
                 : "=f"(d[0]), "=f"(d[1]), "=f"(d[2]), "=f"(d[3])
                 : "r"(a[0]), "r"(a[1]), "r"(a[2]), "r"(a[3]),
                   "r"(b[0]), "r"(b[1]),
                   "f"(c[0]), "f"(c[1]), "f"(c[2]), "f"(c[3]));
}
__device__ __forceinline__ void mma16816h(float* d, const uint32_t* a,
                                          const uint32_t* b, const float* c) {
    asm volatile("mma.sync.aligned.m16n8k16.row.col.f32.f16.f16.f32 "
                 "{%0,%1,%2,%3}, {%4,%5,%6,%7}, {%8,%9}, {%10,%11,%12,%13};"
                 : "=f"(d[0]), "=f"(d[1]), "=f"(d[2]), "=f"(d[3])
                 : "r"(a[0]), "r"(a[1]), "r"(a[2]), "r"(a[3]),
                   "r"(b[0]), "r"(b[1]),
                   "f"(c[0]), "f"(c[1]), "f"(c[2]), "f"(c[3]));
}
__device__ __forceinline__ uint32_t pack2(float a, float b) {
    __nv_bfloat16 x = __float2bfloat16(a), y = __float2bfloat16(b);
    uint16_t ux = *(uint16_t*)&x, uy = *(uint16_t*)&y;
    return (uint32_t)ux | ((uint32_t)uy << 16);
}
__device__ __forceinline__ uint32_t pack2h(float a, float b) {
    __half2 h = __floats2half2_rn(a, b);
    return *(uint32_t*)&h;
}

// =====================================================================
// fp32 -> fp16 (vectorized x4)
// =====================================================================
__global__ __launch_bounds__(256) void conv_f16(
    const float4* __restrict__ in, uint2* __restrict__ out, size_t n4)
{
    for (size_t i = (size_t)blockIdx.x * blockDim.x + threadIdx.x; i < n4;
         i += (size_t)gridDim.x * blockDim.x) {
        float4 v = in[i];
        uint2 o;
        o.x = pack2h(v.x, v.y);
        o.y = pack2h(v.z, v.w);
        out[i] = o;
    }
}

// =====================================================================
// fp16 GEMM: C[M,N] = A[M,K] @ B[N,K]^T + bias
// CTA 128x128, 8 warps (2m x 4n), BK=64, 3-stage cp.async, 2 CTA/SM.
// tiles: 128 rows x 128 bytes (64 halves), 8 segs of 16B per row.
// =====================================================================
#define GBK 64
#define GTILE 16384            // 128 * 128 bytes
#define GSTAGE (2*GTILE)       // A, B

__device__ __forceinline__ uint32_t swzg(uint32_t row, uint32_t seg) {
    return row * 128u + ((seg ^ (row & 7u)) * 16u);
}

__global__ __launch_bounds__(256, 2) void gemm_f16(
    const __half* __restrict__ A16, const __half* __restrict__ B16,
    const float* __restrict__ bias, float* __restrict__ C, int N, int K)
{
    extern __shared__ __align__(128) char smem[];
    const uint32_t sb = smem_to_u32(smem);
    const int tid = threadIdx.x;
    const int wid = tid >> 5, lane = tid & 31;
    const int wm = wid & 1, wn = wid >> 1;
    const int bm = blockIdx.y * 128, bn = blockIdx.x * 128;

    const __half* srcA = A16 + (size_t)bm * K;
    const __half* srcB = B16 + (size_t)bn * K;

    // cp.async: 1024 segs per tile, 256 threads -> 4 segs/thread (same row)
    const uint32_t r0 = (uint32_t)tid >> 1;           // 0..127
    const uint32_t s0 = ((uint32_t)tid & 1) * 4;      // 0 or 4

    // prologue: stages 0,1
    #pragma unroll
    for (int s = 0; s < 2; ++s) {
        const int k0 = s * GBK;
        uint32_t da = sb + (uint32_t)s * GSTAGE;
        uint32_t db = da + GTILE;
        const __half* ga = srcA + (size_t)r0 * K + k0;
        const __half* gb = srcB + (size_t)r0 * K + k0;
        #pragma unroll
        for (int i = 0; i < 4; ++i) {
            cp16(da + swzg(r0, s0 + i), ga + (s0 + i) * 8);
            cp16(db + swzg(r0, s0 + i), gb + (s0 + i) * 8);
        }
        CP_COMMIT();
    }

    float acc[4][4][4];
    #pragma unroll
    for (int i = 0; i < 4; ++i)
        #pragma unroll
        for (int j = 0; j < 4; ++j)
            #pragma unroll
            for (int e = 0; e < 4; ++e) acc[i][j][e] = 0.f;

    const uint32_t a_row = (uint32_t)(wm * 64 + (lane & 15));
    const uint32_t a_segl = (uint32_t)(lane >> 4);
    const uint32_t b_row = (uint32_t)(wn * 32 + ((lane >> 4) << 3) + (lane & 7));
    const uint32_t b_segl = (uint32_t)((lane >> 3) & 1);

    const int nchunk = K / GBK;   // 48
    int slot = 0;
    for (int t = 0; t < nchunk; ++t) {
        if (t + 1 < nchunk) CP_WAIT1(); else CP_WAIT0();
        __syncthreads();

        // prefetch chunk t+2 into slot (slot+2)%3
        if (t + 2 < nchunk) {
            int ps = slot + 2; if (ps >= 3) ps -= 3;
            const int k0 = (t + 2) * GBK;
            uint32_t da = sb + (uint32_t)ps * GSTAGE;
            uint32_t db = da + GTILE;
            const __half* ga = srcA + (size_t)r0 * K + k0;
            const __half* gb = srcB + (size_t)r0 * K + k0;
            #pragma unroll
            for (int i = 0; i < 4; ++i) {
                cp16(da + swzg(r0, s0 + i), ga + (s0 + i) * 8);
                cp16(db + swzg(r0, s0 + i), gb + (s0 + i) * 8);
            }
            CP_COMMIT();
        }

        const uint32_t At = sb + (uint32_t)slot * GSTAGE;
        const uint32_t Bt = At + GTILE;

        #pragma unroll
        for (int ks = 0; ks < 4; ++ks) {
            uint32_t af[4][4], bf[4][2];
            #pragma unroll
            for (int mi = 0; mi < 4; ++mi)
                ldmat4(af[mi], At + swzg(a_row + mi * 16, a_segl + ks * 2));
            #pragma unroll
            for (int njp = 0; njp < 2; ++njp) {
                uint32_t rb[4];
                ldmat4(rb, Bt + swzg(b_row + njp * 16, b_segl + ks * 2));
                bf[njp*2][0] = rb[0]; bf[njp*2][1] = rb[1];
                bf[njp*2+1][0] = rb[2]; bf[njp*2+1][1] = rb[3];
            }
            #pragma unroll
            for (int mi = 0; mi < 4; ++mi)
                #pragma unroll
                for (int nj = 0; nj < 4; ++nj)
                    mma16816h(acc[mi][nj], af[mi], bf[nj], acc[mi][nj]);
        }
        ++slot; if (slot >= 3) slot = 0;
    }

    const int g = lane >> 2, tc = lane & 3;
    #pragma unroll
    for (int mi = 0; mi < 4; ++mi) {
        int row = bm + wm * 64 + mi * 16 + g;
        #pragma unroll
        for (int nj = 0; nj < 4; ++nj) {
            int col = bn + wn * 32 + nj * 8 + tc * 2;
            float b0 = bias[col], b1 = bias[col + 1];
            float2 v0 = make_float2(acc[mi][nj][0] + b0, acc[mi][nj][1] + b1);
            float2 v1 = make_float2(acc[mi][nj][2] + b0, acc[mi][nj][3] + b1);
            *(float2*)(C + (size_t)row * N + col) = v0;
            *(float2*)(C + (size_t)(row + 8) * N + col) = v1;
        }
    }
}

// =====================================================================
// RMSNorm(q,k) + RoPE; q,k bf16 hi/lo [BH,L,D]; v transposed [BH,D,L].
// =====================================================================
__global__ __launch_bounds__(128) void qkv_post(
    const float* __restrict__ pe, const float* __restrict__ qscale,
    const float* __restrict__ kscale)
{
    __shared__ float sq[128], sk[128], qs[128], ks[128];
    const int idx = blockIdx.x;
    const int h = idx % HEADS;
    const int l = (idx / HEADS) % LL;
    const int b = idx / (HEADS * LL);
    const int d = threadIdx.x;

    const size_t row = (size_t)(b * LL + l) * NQKV;
    float qv = g_qkv[row +           h*HD + d];
    float kv = g_qkv[row + DIM     + h*HD + d];
    float vv = g_qkv[row + 2*DIM   + h*HD + d];

    sq[d] = qv * qv; sk[d] = kv * kv;
    __syncthreads();
    for (int off = 64; off > 0; off >>= 1) {
        if (d < off) { sq[d] += sq[d+off]; sk[d] += sk[d+off]; }
        __syncthreads();
    }
    float rq = rsqrtf(sq[0] * (1.f/HD) + 1e-6f);
    float rk = rsqrtf(sk[0] * (1.f/HD) + 1e-6f);
    qs[d] = qv * rq * qscale[d];
    ks[d] = kv * rk * kscale[d];
    __syncthreads();

    const int p = d >> 1, r = d & 1;
    const float* pe4 = pe + (((size_t)l * 64 + p) * 2 + r) * 2;
    float qo = pe4[0]*qs[2*p] + pe4[1]*qs[2*p+1];
    float ko = pe4[0]*ks[2*p] + pe4[1]*ks[2*p+1];

    const int bh = b * HEADS + h;
    const size_t qk = ((size_t)bh * LL + l) * HD + d;
    __nv_bfloat16 qh = __float2bfloat16(qo);
    g_qhi[qk] = qh;  g_qlo[qk] = __float2bfloat16(qo - __bfloat162float(qh));
    __nv_bfloat16 kh = __float2bfloat16(ko);
    g_khi[qk] = kh;  g_klo[qk] = __float2bfloat16(ko - __bfloat162float(kh));
    const size_t vt = ((size_t)bh * HD + d) * LL + l;
    __nv_bfloat16 vh = __float2bfloat16(vv);
    g_vthi[vt] = vh; g_vtlo[vt] = __float2bfloat16(vv - __bfloat162float(vh));
}

// =====================================================================
// tensor-core flash attention (bf16 hi/lo split, online softmax)
// BM=64, BN=64, D=128, 8 warps.  (validated round 5/6)
// =====================================================================
#define SWZQ(r, s) ((r)*256u + ((uint32_t)((s) ^ ((r) & 7u)) * 16u))   // 256B rows
#define SWZV(r, s) ((r)*128u + ((uint32_t)((s) ^ ((r) & 7u)) * 16u))   // 128B rows

#define F_QHI 0
#define F_QLO 16384
#define F_KHI 32768      // 2 stages x 16384
#define F_KLO 65536
#define F_VHI 98304
#define F_VLO 131072
#define F_SS  163840     // fp32 [64][68] = 17408
#define F_PHI 181248
#define F_PLO 189440
#define F_MR  197632
#define F_LR  197888
#define F_AL  198144
#define F_TOT 198400

__global__ __launch_bounds__(256, 1) void flash_attn_mma()
{
    extern __shared__ __align__(128) char sm[];
    const uint32_t sb = smem_to_u32(sm);
    float* s_S  = (float*)(sm + F_SS);
    float* s_mr = (float*)(sm + F_MR);
    float* s_lr = (float*)(sm + F_LR);
    float* s_al = (float*)(sm + F_AL);

    const int tid = threadIdx.x, lane = tid & 31, wid = tid >> 5;
    const int wm = wid & 1, wn = wid >> 1;
    const int bh = blockIdx.y, qt = blockIdx.x;
    const float scale = 0.08838834764831845f;

    if (tid < 64) { s_mr[tid] = -INFINITY; s_lr[tid] = 0.f; }

    {
        const __nv_bfloat16* qh = g_qhi + ((size_t)bh * LL + (size_t)qt * 64) * HD;
        const __nv_bfloat16* ql = g_qlo + ((size_t)bh * LL + (size_t)qt * 64) * HD;
        uint32_t row = tid >> 2, s0 = (tid & 3) * 4;
        #pragma unroll
        for (int i = 0; i < 4; ++i) {
            cp16(sb + F_QHI + SWZQ(row, s0 + i), qh + (size_t)row * HD + (s0 + i) * 8);
            cp16(sb + F_QLO + SWZQ(row, s0 + i), ql + (size_t)row * HD + (s0 + i) * 8);
        }
    }
    {
        const int t = 0, stage = 0;
        const __nv_bfloat16* kh = g_khi + ((size_t)bh * LL + (size_t)t * 64) * HD;
        const __nv_bfloat16* kl = g_klo + ((size_t)bh * LL + (size_t)t * 64) * HD;
        uint32_t row = tid >> 2, s0 = (tid & 3) * 4;
        #pragma unroll
        for (int i = 0; i < 4; ++i) {
            cp16(sb + F_KHI + stage*16384 + SWZQ(row, s0+i), kh + (size_t)row * HD + (s0+i)*8);
            cp16(sb + F_KLO + stage*16384 + SWZQ(row, s0+i), kl + (size_t)row * HD + (s0+i)*8);
        }
        const __nv_bfloat16* vh = g_vthi + (size_t)bh * HD * LL;
        const __nv_bfloat16* vl = g_vtlo + (size_t)bh * HD * LL;
        uint32_t vrow = tid >> 1, vs0 = (tid & 1) * 4;
        #pragma unroll
        for (int i = 0; i < 4; ++i) {
            cp16(sb + F_VHI + stage*16384 + SWZV(vrow, vs0+i), vh + (size_t)vrow*LL + t*64 + (vs0+i)*8);
            cp16(sb + F_VLO + stage*16384 + SWZV(vrow, vs0+i), vl + (size_t)vrow*LL + t*64 + (vs0+i)*8);
        }
    }
    CP_COMMIT();

    float oa[2][4][4];
    #pragma unroll
    for (int mi = 0; mi < 2; ++mi)
        #pragma unroll
        for (int nj = 0; nj < 4; ++nj)
            #pragma unroll
            for (int e = 0; e < 4; ++e) oa[mi][nj][e] = 0.f;

    const int T = LL / 64;
    for (int t = 0; t < T; ++t) {
        const uint32_t cur = (uint32_t)(t & 1) * 16384u;
        CP_WAIT0();
        __syncthreads();

        // ---- S = Q K^T (3-term split) ----
        {
            const uint32_t Khb = sb + F_KHI + cur;
            const uint32_t Klb = sb + F_KLO + cur;
            float sf[2][2][4];
            #pragma unroll
            for (int mi = 0; mi < 2; ++mi)
                #pragma unroll
                for (int nj = 0; nj < 2; ++nj)
                    #pragma unroll
                    for (int e = 0; e < 4; ++e) sf[mi][nj][e] = 0.f;

            #pragma unroll
            for (int ksi = 0; ksi < 8; ++ksi) {
                uint32_t aseg = ksi * 2 + (lane >> 4);
                uint32_t ah[2][4], al_[2][4];
                #pragma unroll
                for (int mi = 0; mi < 2; ++mi) {
                    uint32_t ar = wm * 32 + mi * 16 + (lane & 15);
                    ldmat4(ah[mi],  sb + F_QHI + SWZQ(ar, aseg));
                    ldmat4(al_[mi], sb + F_QLO + SWZQ(ar, aseg));
                }
                uint32_t br = wn * 16 + ((lane >> 4) << 3) + (lane & 7);
                uint32_t bseg = ksi * 2 + ((lane >> 3) & 1);
                uint32_t rb[4], bh2[2][2], bl2[2][2];
                ldmat4(rb, Khb + SWZQ(br, bseg));
                bh2[0][0]=rb[0]; bh2[0][1]=rb[1]; bh2[1][0]=rb[2]; bh2[1][1]=rb[3];
                ldmat4(rb, Klb + SWZQ(br, bseg));
                bl2[0][0]=rb[0]; bl2[0][1]=rb[1]; bl2[1][0]=rb[2]; bl2[1][1]=rb[3];
                #pragma unroll
                for (int mi = 0; mi < 2; ++mi)
                    #pragma unroll
                    for (int nj = 0; nj < 2; ++nj) {
                        mma16816(sf[mi][nj], ah[mi],  bh2[nj], sf[mi][nj]);
                        mma16816(sf[mi][nj], al_[mi], bh2[nj], sf[mi][nj]);
                        mma16816(sf[mi][nj], ah[mi],  bl2[nj], sf[mi][nj]);
                    }
            }
            #pragma unroll
            for (int mi = 0; mi < 2; ++mi) {
                int r = wm * 32 + mi * 16 + (lane >> 2);
                #pragma unroll
                for (int nj = 0; nj < 2; ++nj) {
                    int c = wn * 16 + nj * 8 + 2 * (lane & 3);
                    *(float2*)&s_S[r * 68 + c]       = make_float2(sf[mi][nj][0], sf[mi][nj][1]);
                    *(float2*)&s_S[(r + 8) * 68 + c] = make_float2(sf[mi][nj][2], sf[mi][nj][3]);
                }
            }
        }

        if (t + 1 < T) {
            const uint32_t stg = (uint32_t)((t + 1) & 1) * 16384u;
            const int tn = t + 1;
            const __nv_bfloat16* kh = g_khi + ((size_t)bh * LL + (size_t)tn * 64) * HD;
            const __nv_bfloat16* kl = g_klo + ((size_t)bh * LL + (size_t)tn * 64) * HD;
            uint32_t row = tid >> 2, s0 = (tid & 3) * 4;
            #pragma unroll
            for (int i = 0; i < 4; ++i) {
                cp16(sb + F_KHI + stg + SWZQ(row, s0+i), kh + (size_t)row * HD + (s0+i)*8);
                cp16(sb + F_KLO + stg + SWZQ(row, s0+i), kl + (size_t)row * HD + (s0+i)*8);
            }
            const __nv_bfloat16* vh = g_vthi + (size_t)bh * HD * LL;
            const __nv_bfloat16* vl = g_vtlo + (size_t)bh * HD * LL;
            uint32_t vrow = tid >> 1, vs0 = (tid & 1) * 4;
            #pragma unroll
            for (int i = 0; i < 4; ++i) {
                cp16(sb + F_VHI + stg + SWZV(vrow, vs0+i), vh + (size_t)vrow*LL + tn*64 + (vs0+i)*8);
                cp16(sb + F_VLO + stg + SWZV(vrow, vs0+i), vl + (size_t)vrow*LL + tn*64 + (vs0+i)*8);
            }
            CP_COMMIT();
        }
        __syncthreads();

        // ---- online softmax ----
        {
            int r = tid >> 2, c0 = (tid & 3) * 16;
            float v[16];
            #pragma unroll
            for (int q = 0; q < 4; ++q) {
                float4 f = *(float4*)&s_S[r * 68 + c0 + q * 4];
                v[q*4+0] = f.x * scale; v[q*4+1] = f.y * scale;
                v[q*4+2] = f.z * scale; v[q*4+3] = f.w * scale;
            }
            float mx = v[0];
            #pragma unroll
            for (int j = 1; j < 16; ++j) mx = fmaxf(mx, v[j]);
            mx = fmaxf(mx, __shfl_xor_sync(0xffffffffu, mx, 1));
            mx = fmaxf(mx, __shfl_xor_sync(0xffffffffu, mx, 2));
            float mold = s_mr[r];
            float mnew = fmaxf(mold, mx);
            float alpha = __expf(mold - mnew);
            float p[16], lo[16], sum = 0.f;
            #pragma unroll
            for (int j = 0; j < 16; ++j) { p[j] = __expf(v[j] - mnew); sum += p[j]; }
            sum += __shfl_xor_sync(0xffffffffu, sum, 1);
            sum += __shfl_xor_sync(0xffffffffu, sum, 2);
            __syncwarp();
            if ((tid & 3) == 0) {
                s_mr[r] = mnew;
                s_lr[r] = s_lr[r] * alpha + sum;
                s_al[r] = alpha;
            }
            #pragma unroll
            for (int j = 0; j < 16; ++j) {
                float ph = __bfloat162float(__float2bfloat16(p[j]));
                lo[j] = p[j] - ph;
            }
            uint32_t seg = (uint32_t)(tid & 3) * 2;
            uint4 u;
            u.x = pack2(p[0],p[1]);  u.y = pack2(p[2],p[3]);
            u.z = pack2(p[4],p[5]);  u.w = pack2(p[6],p[7]);
            *(uint4*)(sm + F_PHI + SWZV((uint32_t)r, seg)) = u;
            u.x = pack2(p[8],p[9]);  u.y = pack2(p[10],p[11]);
            u.z = pack2(p[12],p[13]); u.w = pack2(p[14],p[15]);
            *(uint4*)(sm + F_PHI + SWZV((uint32_t)r, seg + 1)) = u;
            u.x = pack2(lo[0],lo[1]); u.y = pack2(lo[2],lo[3]);
            u.z = pack2(lo[4],lo[5]); u.w = pack2(lo[6],lo[7]);
            *(uint4*)(sm + F_PLO + SWZV((uint32_t)r, seg)) = u;
            u.x = pack2(lo[8],lo[9]); u.y = pack2(lo[10],lo[11]);
            u.z = pack2(lo[12],lo[13]); u.w = pack2(lo[14],lo[15]);
            *(uint4*)(sm + F_PLO + SWZV((uint32_t)r, seg + 1)) = u;
        }
        __syncthreads();

        // ---- O = alpha*O + P V (3-term split) ----
        {
            float aR[2][2];
            #pragma unroll
            for (int mi = 0; mi < 2; ++mi) {
                int r = wm * 32 + mi * 16 + (lane >> 2);
                aR[mi][0] = s_al[r];
                aR[mi][1] = s_al[r + 8];
            }
            #pragma unroll
            for (int mi = 0; mi < 2; ++mi)
                #pragma unroll
                for (int nj = 0; nj < 4; ++nj) {
                    oa[mi][nj][0] *= aR[mi][0]; oa[mi][nj][1] *= aR[mi][0];
                    oa[mi][nj][2] *= aR[mi][1]; oa[mi][nj][3] *= aR[mi][1];
                }
            const uint32_t Vhb = sb + F_VHI + cur;
            const uint32_t Vlb = sb + F_VLO + cur;
            #pragma unroll
            for (int ksi = 0; ksi < 4; ++ksi) {
                uint32_t aseg = ksi * 2 + (lane >> 4);
                uint32_t ph[2][4], pl[2][4];
                #pragma unroll
                for (int mi = 0; mi < 2; ++mi) {
                    uint32_t ar = wm * 32 + mi * 16 + (lane & 15);
                    ldmat4(ph[mi], sb + F_PHI + SWZV(ar, aseg));
                    ldmat4(pl[mi], sb + F_PLO + SWZV(ar, aseg));
                }
                uint32_t bh2[4][2], bl2[4][2];
                #pragma unroll
                for (int njp = 0; njp < 2; ++njp) {
                    uint32_t br = wn * 32 + njp * 16 + ((lane >> 4) << 3) + (lane & 7);
                    uint32_t bseg = ksi * 2 + ((lane >> 3) & 1);
                    uint32_t rb[4];
                    ldmat4(rb, Vhb + SWZV(br, bseg));
                    bh2[njp*2][0]=rb[0]; bh2[njp*2][1]=rb[1];
                    bh2[njp*2+1][0]=rb[2]; bh2[njp*2+1][1]=rb[3];
                    ldmat4(rb, Vlb + SWZV(br, bseg));
                    bl2[njp*2][0]=rb[0]; bl2[njp*2][1]=rb[1];
                    bl2[njp*2+1][0]=rb[2]; bl2[njp*2+1][1]=rb[3];
                }
                #pragma unroll
                for (int mi = 0; mi < 2; ++mi)
                    #pragma unroll
                    for (int nj = 0; nj < 4; ++nj) {
                        mma16816(oa[mi][nj], ph[mi], bh2[nj], oa[mi][nj]);
                        mma16816(oa[mi][nj], pl[mi], bh2[nj], oa[mi][nj]);
                        mma16816(oa[mi][nj], ph[mi], bl2[nj], oa[mi][nj]);
                    }
            }
        }
    }

    // ---- write O as single fp16 into [B, L, DIM] (proj GEMM input) ----
    __syncthreads();
    {
        const int b = bh / HEADS, h = bh % HEADS;
        #pragma unroll
        for (int mi = 0; mi < 2; ++mi) {
            int rloc = wm * 32 + mi * 16 + (lane >> 2);
            float inv0 = 1.f / s_lr[rloc];
            float inv1 = 1.f / s_lr[rloc + 8];
            size_t grow0 = (size_t)(b * LL + qt * 64 + rloc) * DIM;
            size_t grow1 = grow0 + (size_t)8 * DIM;
            #pragma unroll
            for (int nj = 0; nj < 4; ++nj) {
                int col = h * HD + wn * 32 + nj * 8 + 2 * (lane & 3);
                *(uint32_t*)&g_a16[grow0 + col] =
                    pack2h(oa[mi][nj][0] * inv0, oa[mi][nj][1] * inv0);
                *(uint32_t*)&g_a16[grow1 + col] =
                    pack2h(oa[mi][nj][2] * inv1, oa[mi][nj][3] * inv1);
            }
        }
    }
}

// =====================================================================
// launch
// =====================================================================
extern "C" void kernel_launch(void* const* d_in, const int* in_sizes, int n_in,
                              void* d_out, int out_size)
{
    const float* x      = (const float*)d_in[0];
    const float* pe     = (const float*)d_in[1];
    const float* Wqkv   = (const float*)d_in[2];
    const float* bqkv   = (const float*)d_in[3];
    const float* qscale = (const float*)d_in[4];
    const float* kscale = (const float*)d_in[5];
    const float* Wproj  = (const float*)d_in[6];
    const float* bproj  = (const float*)d_in[7];
    float* out = (float*)d_out;

    float* qkv_p;
    cudaGetSymbolAddress((void**)&qkv_p, g_qkv);
    __half *x16, *wq16, *wp16, *a16;
    cudaGetSymbolAddress((void**)&x16,  g_x16);
    cudaGetSymbolAddress((void**)&wq16, g_wq16);
    cudaGetSymbolAddress((void**)&wp16, g_wp16);
    cudaGetSymbolAddress((void**)&a16,  g_a16);

    cudaFuncSetAttribute(gemm_f16, cudaFuncAttributeMaxDynamicSharedMemorySize,
                         3 * GSTAGE);
    cudaFuncSetAttribute(flash_attn_mma, cudaFuncAttributeMaxDynamicSharedMemorySize,
                         F_TOT);

    // 0) fp16 conversions
    conv_f16<<<1024, 256>>>((const float4*)x,     (uint2*)x16,  (size_t)MTOT * DIM / 4);
    conv_f16<<<1024, 256>>>((const float4*)Wqkv,  (uint2*)wq16, (size_t)NQKV * DIM / 4);
    conv_f16<<<1024, 256>>>((const float4*)Wproj, (uint2*)wp16, (size_t)DIM * DIM / 4);

    // 1) QKV GEMM (fp16)
    gemm_f16<<<dim3(NQKV/128, MTOT/128), 256, 3 * GSTAGE>>>(
        x16, wq16, bqkv, qkv_p, NQKV, DIM);

    // 2) RMSNorm + RoPE + transpose + bf16 hi/lo
    qkv_post<<<BB*LL*HEADS, 128>>>(pe, qscale, kscale);

    // 3) tensor-core flash attention -> g_a16 (fp16)
    flash_attn_mma<<<dim3(LL/64, BH), 256, F_TOT>>>();

    // 4) proj GEMM (fp16)
    gemm_f16<<<dim3(DIM/128, MTOT/128), 256, 3 * GSTAGE>>>(
        a16, wp16, bproj, out, DIM, DIM);
}

// round 8
// speedup vs baseline: 4.5862x; 1.1514x over previous
#include <cuda_runtime.h>
#include <cuda_bf16.h>
#include <cuda_fp16.h>
#include <cstdint>
#include <math.h>

#define DIM   3072
#define HEADS 24
#define HD    128
#define BB    2
#define LL    2048
#define MTOT  (BB*LL)          // 4096 rows
#define NQKV  (3*DIM)          // 9216
#define BH    (BB*HEADS)       // 48

// ---------------- scratch (static device globals; no runtime alloc) ----------------
__device__ float g_qkv[(size_t)MTOT * NQKV];        // [B*L, 3*DIM]

__device__ __half g_x16 [(size_t)MTOT * DIM];       // x fp16
__device__ __half g_wq16[(size_t)NQKV * DIM];       // Wqkv fp16
__device__ __half g_wp16[(size_t)DIM * DIM];        // Wproj fp16
__device__ __half g_a16 [(size_t)MTOT * DIM];       // attention out fp16

__device__ __nv_bfloat16 g_qhi [(size_t)BH*LL*HD];  // [BH, L, D] (scaled by 1/sqrt(d))
__device__ __nv_bfloat16 g_qlo [(size_t)BH*LL*HD];
__device__ __nv_bfloat16 g_khi [(size_t)BH*LL*HD];
__device__ __nv_bfloat16 g_klo [(size_t)BH*LL*HD];
__device__ __nv_bfloat16 g_vthi[(size_t)BH*HD*LL];  // [BH, D, L] (transposed)
__device__ __nv_bfloat16 g_vtlo[(size_t)BH*HD*LL];

// ====================== helpers ======================
__device__ __forceinline__ uint32_t smem_to_u32(const void* p) {
    uint32_t a;
    asm("{ .reg .u64 t; cvta.to.shared.u64 t, %1; cvt.u32.u64 %0, t; }" : "=r"(a) : "l"(p));
    return a;
}
__device__ __forceinline__ void cp16(uint32_t s, const void* g) {
    asm volatile("cp.async.cg.shared.global [%0], [%1], 16;\n" :: "r"(s), "l"(g));
}
#define CP_COMMIT() asm volatile("cp.async.commit_group;\n" ::: "memory")
#define CP_WAIT1()  asm volatile("cp.async.wait_group 1;\n" ::: "memory")
#define CP_WAIT0()  asm volatile("cp.async.wait_group 0;\n" ::: "memory")

__device__ __forceinline__ void ldmat4(uint32_t* r, uint32_t addr) {
    asm volatile("ldmatrix.sync.aligned.m8n8.x4.shared.b16 {%0,%1,%2,%3}, [%4];"
                 : "=r"(r[0]), "=r"(r[1]), "=r"(r[2]), "=r"(r[3]) : "r"(addr));
}
__device__ __forceinline__ void mma16816(float* d, const uint32_t* a,
                                         const uint32_t* b, const float* c) {
    asm volatile("mma.sync.aligned.m16n8k16.row.col.f32.bf16.bf16.f32 "
                 "{%0,%1,%2,%3}, {%4,%5,%6,%7}, {%8,%9}, {%10,%11,%12,%13};"
                 : "=f"(d[0]), "=f"(d[1]), "=f"(d[2]), "=f"(d[3])
                 : "r"(a[0]), "r"(a[1]), "r"(a[2]), "r"(a[3]),
                   "r"(b[0]), "r"(b[1]),
                   "f"(c[0]), "f"(c[1]), "f"(c[2]), "f"(c[3]));
}
__device__ __forceinline__ void mma16816h(float* d, const uint32_t* a,
                                          const uint32_t* b, const float* c) {
    asm volatile("mma.sync.aligned.m16n8k16.row.col.f32.f16.f16.f32 "
                 "{%0,%1,%2,%3}, {%4,%5,%6,%7}, {%8,%9}, {%10,%11,%12,%13};"
                 : "=f"(d[0]), "=f"(d[1]), "=f"(d[2]), "=f"(d[3])
                 : "r"(a[0]), "r"(a[1]), "r"(a[2]), "r"(a[3]),
                   "r"(b[0]), "r"(b[1]),
                   "f"(c[0]), "f"(c[1]), "f"(c[2]), "f"(c[3]));
}
__device__ __forceinline__ uint32_t pack2(float a, float b) {
    __nv_bfloat16 x = __float2bfloat16(a), y = __float2bfloat16(b);
    uint16_t ux = *(uint16_t*)&x, uy = *(uint16_t*)&y;
    return (uint32_t)ux | ((uint32_t)uy << 16);
}
__device__ __forceinline__ uint32_t pack2h(float a, float b) {
    __half2 h = __floats2half2_rn(a, b);
    return *(uint32_t*)&h;
}

// =====================================================================
// fp32 -> fp16 (vectorized x4)
// =====================================================================
__global__ __launch_bounds__(256) void conv_f16(
    const float4* __restrict__ in, uint2* __restrict__ out, size_t n4)
{
    for (size_t i = (size_t)blockIdx.x * blockDim.x + threadIdx.x; i < n4;
         i += (size_t)gridDim.x * blockDim.x) {
        float4 v = in[i];
        uint2 o;
        o.x = pack2h(v.x, v.y);
        o.y = pack2h(v.z, v.w);
        out[i] = o;
    }
}

// =====================================================================
// fp16 GEMM (validated round 7): C = A @ B^T + bias
// =====================================================================
#define GBK 64
#define GTILE 16384
#define GSTAGE (2*GTILE)

__device__ __forceinline__ uint32_t swzg(uint32_t row, uint32_t seg) {
    return row * 128u + ((seg ^ (row & 7u)) * 16u);
}

__global__ __launch_bounds__(256, 2) void gemm_f16(
    const __half* __restrict__ A16, const __half* __restrict__ B16,
    const float* __restrict__ bias, float* __restrict__ C, int N, int K)
{
    extern __shared__ __align__(128) char smem[];
    const uint32_t sb = smem_to_u32(smem);
    const int tid = threadIdx.x;
    const int wid = tid >> 5, lane = tid & 31;
    const int wm = wid & 1, wn = wid >> 1;
    const int bm = blockIdx.y * 128, bn = blockIdx.x * 128;

    const __half* srcA = A16 + (size_t)bm * K;
    const __half* srcB = B16 + (size_t)bn * K;

    const uint32_t r0 = (uint32_t)tid >> 1;
    const uint32_t s0 = ((uint32_t)tid & 1) * 4;

    #pragma unroll
    for (int s = 0; s < 2; ++s) {
        const int k0 = s * GBK;
        uint32_t da = sb + (uint32_t)s * GSTAGE;
        uint32_t db = da + GTILE;
        const __half* ga = srcA + (size_t)r0 * K + k0;
        const __half* gb = srcB + (size_t)r0 * K + k0;
        #pragma unroll
        for (int i = 0; i < 4; ++i) {
            cp16(da + swzg(r0, s0 + i), ga + (s0 + i) * 8);
            cp16(db + swzg(r0, s0 + i), gb + (s0 + i) * 8);
        }
        CP_COMMIT();
    }

    float acc[4][4][4];
    #pragma unroll
    for (int i = 0; i < 4; ++i)
        #pragma unroll
        for (int j = 0; j < 4; ++j)
            #pragma unroll
            for (int e = 0; e < 4; ++e) acc[i][j][e] = 0.f;

    const uint32_t a_row = (uint32_t)(wm * 64 + (lane & 15));
    const uint32_t a_segl = (uint32_t)(lane >> 4);
    const uint32_t b_row = (uint32_t)(wn * 32 + ((lane >> 4) << 3) + (lane & 7));
    const uint32_t b_segl = (uint32_t)((lane >> 3) & 1);

    const int nchunk = K / GBK;
    int slot = 0;
    for (int t = 0; t < nchunk; ++t) {
        if (t + 1 < nchunk) CP_WAIT1(); else CP_WAIT0();
        __syncthreads();

        if (t + 2 < nchunk) {
            int ps = slot + 2; if (ps >= 3) ps -= 3;
            const int k0 = (t + 2) * GBK;
            uint32_t da = sb + (uint32_t)ps * GSTAGE;
            uint32_t db = da + GTILE;
            const __half* ga = srcA + (size_t)r0 * K + k0;
            const __half* gb = srcB + (size_t)r0 * K + k0;
            #pragma unroll
            for (int i = 0; i < 4; ++i) {
                cp16(da + swzg(r0, s0 + i), ga + (s0 + i) * 8);
                cp16(db + swzg(r0, s0 + i), gb + (s0 + i) * 8);
            }
            CP_COMMIT();
        }

        const uint32_t At = sb + (uint32_t)slot * GSTAGE;
        const uint32_t Bt = At + GTILE;

        #pragma unroll
        for (int ks = 0; ks < 4; ++ks) {
            uint32_t af[4][4], bf[4][2];
            #pragma unroll
            for (int mi = 0; mi < 4; ++mi)
                ldmat4(af[mi], At + swzg(a_row + mi * 16, a_segl + ks * 2));
            #pragma unroll
            for (int njp = 0; njp < 2; ++njp) {
                uint32_t rb[4];
                ldmat4(rb, Bt + swzg(b_row + njp * 16, b_segl + ks * 2));
                bf[njp*2][0] = rb[0]; bf[njp*2][1] = rb[1];
                bf[njp*2+1][0] = rb[2]; bf[njp*2+1][1] = rb[3];
            }
            #pragma unroll
            for (int mi = 0; mi < 4; ++mi)
                #pragma unroll
                for (int nj = 0; nj < 4; ++nj)
                    mma16816h(acc[mi][nj], af[mi], bf[nj], acc[mi][nj]);
        }
        ++slot; if (slot >= 3) slot = 0;
    }

    const int g = lane >> 2, tc = lane & 3;
    #pragma unroll
    for (int mi = 0; mi < 4; ++mi) {
        int row = bm + wm * 64 + mi * 16 + g;
        #pragma unroll
        for (int nj = 0; nj < 4; ++nj) {
            int col = bn + wn * 32 + nj * 8 + tc * 2;
            float b0 = bias[col], b1 = bias[col + 1];
            float2 v0 = make_float2(acc[mi][nj][0] + b0, acc[mi][nj][1] + b1);
            float2 v1 = make_float2(acc[mi][nj][2] + b0, acc[mi][nj][3] + b1);
            *(float2*)(C + (size_t)row * N + col) = v0;
            *(float2*)(C + (size_t)(row + 8) * N + col) = v1;
        }
    }
}

// =====================================================================
// RMSNorm(q,k) + RoPE; q scaled by 1/sqrt(d); q,k bf16 hi/lo [BH,L,D];
// v transposed [BH,D,L].
// =====================================================================
__global__ __launch_bounds__(128) void qkv_post(
    const float* __restrict__ pe, const float* __restrict__ qscale,
    const float* __restrict__ kscale)
{
    __shared__ float sq[128], sk[128], qs[128], ks[128];
    const int idx = blockIdx.x;
    const int h = idx % HEADS;
    const int l = (idx / HEADS) % LL;
    const int b = idx / (HEADS * LL);
    const int d = threadIdx.x;

    const size_t row = (size_t)(b * LL + l) * NQKV;
    float qv = g_qkv[row +           h*HD + d];
    float kv = g_qkv[row + DIM     + h*HD + d];
    float vv = g_qkv[row + 2*DIM   + h*HD + d];

    sq[d] = qv * qv; sk[d] = kv * kv;
    __syncthreads();
    for (int off = 64; off > 0; off >>= 1) {
        if (d < off) { sq[d] += sq[d+off]; sk[d] += sk[d+off]; }
        __syncthreads();
    }
    float rq = rsqrtf(sq[0] * (1.f/HD) + 1e-6f);
    float rk = rsqrtf(sk[0] * (1.f/HD) + 1e-6f);
    qs[d] = qv * rq * qscale[d];
    ks[d] = kv * rk * kscale[d];
    __syncthreads();

    const int p = d >> 1, r = d & 1;
    const float* pe4 = pe + (((size_t)l * 64 + p) * 2 + r) * 2;
    float qo = (pe4[0]*qs[2*p] + pe4[1]*qs[2*p+1]) * 0.08838834764831845f;
    float ko = pe4[0]*ks[2*p] + pe4[1]*ks[2*p+1];

    const int bh = b * HEADS + h;
    const size_t qk = ((size_t)bh * LL + l) * HD + d;
    __nv_bfloat16 qh = __float2bfloat16(qo);
    g_qhi[qk] = qh;  g_qlo[qk] = __float2bfloat16(qo - __bfloat162float(qh));
    __nv_bfloat16 kh = __float2bfloat16(ko);
    g_khi[qk] = kh;  g_klo[qk] = __float2bfloat16(ko - __bfloat162float(kh));
    const size_t vt = ((size_t)bh * HD + d) * LL + l;
    __nv_bfloat16 vh = __float2bfloat16(vv);
    g_vthi[vt] = vh; g_vtlo[vt] = __float2bfloat16(vv - __bfloat162float(vh));
}

// =====================================================================
// FA2-style flash attention: BM=128, BN=64, 8 warps; each warp owns a
// 16-row x 64-col S stripe; softmax fully in registers; S-frags
// reinterpreted as PV A-frags (no S/P smem).  bf16 3-term split.
// =====================================================================
#define SWZQ(r, s) ((r)*256u + ((uint32_t)((s) ^ ((r) & 7u)) * 16u))   // 256B rows
#define SWZV(r, s) ((r)*128u + ((uint32_t)((s) ^ ((r) & 7u)) * 16u))   // 128B rows

#define G_QHI 0
#define G_QLO 32768
#define G_KST 65536          // per stage: Khi, Klo(+16384), Vhi(+32768), Vlo(+49152)
#define G_STRIDE 65536
#define F2_TOT (G_KST + 2*G_STRIDE)   // 196608

__device__ __forceinline__ void fa_load_kv(uint32_t sb, int bh, int t, int stage,
                                           int tid)
{
    const uint32_t base = sb + G_KST + (uint32_t)stage * G_STRIDE;
    const __nv_bfloat16* kh = g_khi + ((size_t)bh * LL + (size_t)t * 64) * HD;
    const __nv_bfloat16* kl = g_klo + ((size_t)bh * LL + (size_t)t * 64) * HD;
    uint32_t row = (uint32_t)tid >> 2, s0 = ((uint32_t)tid & 3) * 4;
    #pragma unroll
    for (int i = 0; i < 4; ++i) {
        cp16(base + SWZQ(row, s0 + i),         kh + (size_t)row * HD + (s0 + i) * 8);
        cp16(base + 16384 + SWZQ(row, s0 + i), kl + (size_t)row * HD + (s0 + i) * 8);
    }
    const __nv_bfloat16* vh = g_vthi + (size_t)bh * HD * LL;
    const __nv_bfloat16* vl = g_vtlo + (size_t)bh * HD * LL;
    uint32_t vrow = (uint32_t)tid >> 1, vs0 = ((uint32_t)tid & 1) * 4;
    #pragma unroll
    for (int i = 0; i < 4; ++i) {
        cp16(base + 32768 + SWZV(vrow, vs0 + i),
             vh + (size_t)vrow * LL + t * 64 + (vs0 + i) * 8);
        cp16(base + 49152 + SWZV(vrow, vs0 + i),
             vl + (size_t)vrow * LL + t * 64 + (vs0 + i) * 8);
    }
}

__global__ __launch_bounds__(256, 1) void flash_attn_v2()
{
    extern __shared__ __align__(128) char sm[];
    const uint32_t sb = smem_to_u32(sm);
    const int tid = threadIdx.x, lane = tid & 31, wid = tid >> 5;
    const int bh = blockIdx.y, qt = blockIdx.x;

    // prologue: Q tile (128 x 128, hi/lo) + KV stage 0
    {
        const __nv_bfloat16* qh = g_qhi + ((size_t)bh * LL + (size_t)qt * 128) * HD;
        const __nv_bfloat16* ql = g_qlo + ((size_t)bh * LL + (size_t)qt * 128) * HD;
        uint32_t row = (uint32_t)tid >> 1, s0 = ((uint32_t)tid & 1) * 8;
        #pragma unroll
        for (int i = 0; i < 8; ++i) {
            cp16(sb + G_QHI + SWZQ(row, s0 + i), qh + (size_t)row * HD + (s0 + i) * 8);
            cp16(sb + G_QLO + SWZQ(row, s0 + i), ql + (size_t)row * HD + (s0 + i) * 8);
        }
        fa_load_kv(sb, bh, 0, 0, tid);
        CP_COMMIT();
    }
    CP_WAIT0();
    __syncthreads();

    // Q hi fragments -> registers (Qlo re-ldsm'd per iter; Q smem persists)
    uint32_t qhf[8][4];
    const uint32_t ar = (uint32_t)(wid * 16 + (lane & 15));
    #pragma unroll
    for (int ks = 0; ks < 8; ++ks)
        ldmat4(qhf[ks], sb + G_QHI + SWZQ(ar, ks * 2 + (lane >> 4)));

    float oa[16][4];
    #pragma unroll
    for (int dj = 0; dj < 16; ++dj)
        #pragma unroll
        for (int e = 0; e < 4; ++e) oa[dj][e] = 0.f;
    float m0 = -INFINITY, m1 = -INFINITY, l0 = 0.f, l1 = 0.f;

    const uint32_t b_base = ((uint32_t)((lane >> 4) << 3)) + (uint32_t)(lane & 7);
    const uint32_t b_sl = (uint32_t)((lane >> 3) & 1);

    const int T = LL / 64;   // 32
    for (int t = 0; t < T; ++t) {
        if (t > 0) { CP_WAIT0(); __syncthreads(); }
        const uint32_t cur = (uint32_t)(t & 1);
        const uint32_t Kh = sb + G_KST + cur * G_STRIDE;
        const uint32_t Kl = Kh + 16384;
        const uint32_t Vh = Kh + 32768;
        const uint32_t Vl = Kh + 49152;

        if (t + 1 < T) { fa_load_kv(sb, bh, t + 1, 1 - (int)cur, tid); CP_COMMIT(); }

        // ---- S = Q K^T (3-term) ; warp owns 16 rows x 64 cols ----
        float sf[8][4];
        #pragma unroll
        for (int nj = 0; nj < 8; ++nj)
            #pragma unroll
            for (int e = 0; e < 4; ++e) sf[nj][e] = 0.f;

        #pragma unroll
        for (int ks = 0; ks < 8; ++ks) {
            uint32_t qlf[4];
            ldmat4(qlf, sb + G_QLO + SWZQ(ar, ks * 2 + (lane >> 4)));
            #pragma unroll
            for (int njp = 0; njp < 4; ++njp) {
                uint32_t br = (uint32_t)(njp * 16) + b_base;
                uint32_t bseg = (uint32_t)(ks * 2) + b_sl;
                uint32_t kh4[4], kl4[4];
                ldmat4(kh4, Kh + SWZQ(br, bseg));
                ldmat4(kl4, Kl + SWZQ(br, bseg));
                mma16816(sf[njp*2],   qhf[ks], kh4,     sf[njp*2]);
                mma16816(sf[njp*2],   qlf,     kh4,     sf[njp*2]);
                mma16816(sf[njp*2],   qhf[ks], kl4,     sf[njp*2]);
                mma16816(sf[njp*2+1], qhf[ks], kh4 + 2, sf[njp*2+1]);
                mma16816(sf[njp*2+1], qlf,     kh4 + 2, sf[njp*2+1]);
                mma16816(sf[njp*2+1], qhf[ks], kl4 + 2, sf[njp*2+1]);
            }
        }

        // ---- in-register online softmax (rows g = lane>>2, g+8) ----
        float mx0 = sf[0][0], mx1 = sf[0][2];
        #pragma unroll
        for (int nj = 0; nj < 8; ++nj) {
            mx0 = fmaxf(mx0, fmaxf(sf[nj][0], sf[nj][1]));
            mx1 = fmaxf(mx1, fmaxf(sf[nj][2], sf[nj][3]));
        }
        mx0 = fmaxf(mx0, __shfl_xor_sync(0xffffffffu, mx0, 1));
        mx0 = fmaxf(mx0, __shfl_xor_sync(0xffffffffu, mx0, 2));
        mx1 = fmaxf(mx1, __shfl_xor_sync(0xffffffffu, mx1, 1));
        mx1 = fmaxf(mx1, __shfl_xor_sync(0xffffffffu, mx1, 2));
        float mn0 = fmaxf(m0, mx0), mn1 = fmaxf(m1, mx1);
        float a0 = __expf(m0 - mn0), a1 = __expf(m1 - mn1);
        m0 = mn0; m1 = mn1;
        float sum0 = 0.f, sum1 = 0.f;
        #pragma unroll
        for (int nj = 0; nj < 8; ++nj) {
            sf[nj][0] = __expf(sf[nj][0] - mn0); sum0 += sf[nj][0];
            sf[nj][1] = __expf(sf[nj][1] - mn0); sum0 += sf[nj][1];
            sf[nj][2] = __expf(sf[nj][2] - mn1); sum1 += sf[nj][2];
            sf[nj][3] = __expf(sf[nj][3] - mn1); sum1 += sf[nj][3];
        }
        sum0 += __shfl_xor_sync(0xffffffffu, sum0, 1);
        sum0 += __shfl_xor_sync(0xffffffffu, sum0, 2);
        sum1 += __shfl_xor_sync(0xffffffffu, sum1, 1);
        sum1 += __shfl_xor_sync(0xffffffffu, sum1, 2);
        l0 = l0 * a0 + sum0;
        l1 = l1 * a1 + sum1;
        #pragma unroll
        for (int dj = 0; dj < 16; ++dj) {
            oa[dj][0] *= a0; oa[dj][1] *= a0;
            oa[dj][2] *= a1; oa[dj][3] *= a1;
        }

        // ---- pack P: S C-frags -> PV A-frags (bf16 hi + lo) ----
        uint32_t pah[4][4], pal[4][4];
        #pragma unroll
        for (int k2 = 0; k2 < 4; ++k2) {
            #pragma unroll
            for (int half = 0; half < 2; ++half) {
                int nj = k2 * 2 + half;
                float p0 = sf[nj][0], p1 = sf[nj][1];
                float p2 = sf[nj][2], p3 = sf[nj][3];
                pah[k2][half*2+0] = pack2(p0, p1);
                pah[k2][half*2+1] = pack2(p2, p3);
                float h0 = __bfloat162float(__float2bfloat16(p0));
                float h1 = __bfloat162float(__float2bfloat16(p1));
                float h2 = __bfloat162float(__float2bfloat16(p2));
                float h3 = __bfloat162float(__float2bfloat16(p3));
                pal[k2][half*2+0] = pack2(p0 - h0, p1 - h1);
                pal[k2][half*2+1] = pack2(p2 - h2, p3 - h3);
            }
        }

        // ---- O += P V (3-term) ----
        #pragma unroll
        for (int k2 = 0; k2 < 4; ++k2) {
            #pragma unroll
            for (int djp = 0; djp < 8; ++djp) {
                uint32_t br = (uint32_t)(djp * 16) + b_base;
                uint32_t bseg = (uint32_t)(k2 * 2) + b_sl;
                uint32_t vh4[4], vl4[4];
                ldmat4(vh4, Vh + SWZV(br, bseg));
                ldmat4(vl4, Vl + SWZV(br, bseg));
                mma16816(oa[djp*2],   pah[k2], vh4,     oa[djp*2]);
                mma16816(oa[djp*2],   pal[k2], vh4,     oa[djp*2]);
                mma16816(oa[djp*2],   pah[k2], vl4,     oa[djp*2]);
                mma16816(oa[djp*2+1], pah[k2], vh4 + 2, oa[djp*2+1]);
                mma16816(oa[djp*2+1], pal[k2], vh4 + 2, oa[djp*2+1]);
                mma16816(oa[djp*2+1], pah[k2], vl4 + 2, oa[djp*2+1]);
            }
        }
    }

    // ---- epilogue: O/l -> g_a16 [B, L, DIM] ----
    {
        const int b = bh / HEADS, h = bh % HEADS;
        const int g = lane >> 2, tc = lane & 3;
        float inv0 = 1.f / l0, inv1 = 1.f / l1;
        int row0 = qt * 128 + wid * 16 + g;
        size_t gr0 = (size_t)(b * LL + row0) * DIM;
        size_t gr1 = gr0 + (size_t)8 * DIM;
        #pragma unroll
        for (int dj = 0; dj < 16; ++dj) {
            int col = h * HD + dj * 8 + tc * 2;
            *(uint32_t*)&g_a16[gr0 + col] = pack2h(oa[dj][0] * inv0, oa[dj][1] * inv0);
            *(uint32_t*)&g_a16[gr1 + col] = pack2h(oa[dj][2] * inv1, oa[dj][3] * inv1);
        }
    }
}

// =====================================================================
// launch
// =====================================================================
extern "C" void kernel_launch(void* const* d_in, const int* in_sizes, int n_in,
                              void* d_out, int out_size)
{
    const float* x      = (const float*)d_in[0];
    const float* pe     = (const float*)d_in[1];
    const float* Wqkv   = (const float*)d_in[2];
    const float* bqkv   = (const float*)d_in[3];
    const float* qscale = (const float*)d_in[4];
    const float* kscale = (const float*)d_in[5];
    const float* Wproj  = (const float*)d_in[6];
    const float* bproj  = (const float*)d_in[7];
    float* out = (float*)d_out;

    float* qkv_p;
    cudaGetSymbolAddress((void**)&qkv_p, g_qkv);
    __half *x16, *wq16, *wp16, *a16;
    cudaGetSymbolAddress((void**)&x16,  g_x16);
    cudaGetSymbolAddress((void**)&wq16, g_wq16);
    cudaGetSymbolAddress((void**)&wp16, g_wp16);
    cudaGetSymbolAddress((void**)&a16,  g_a16);

    cudaFuncSetAttribute(gemm_f16, cudaFuncAttributeMaxDynamicSharedMemorySize,
                         3 * GSTAGE);
    cudaFuncSetAttribute(flash_attn_v2, cudaFuncAttributeMaxDynamicSharedMemorySize,
                         F2_TOT);

    // 0) fp16 conversions
    conv_f16<<<1024, 256>>>((const float4*)x,     (uint2*)x16,  (size_t)MTOT * DIM / 4);
    conv_f16<<<1024, 256>>>((const float4*)Wqkv,  (uint2*)wq16, (size_t)NQKV * DIM / 4);
    conv_f16<<<1024, 256>>>((const float4*)Wproj, (uint2*)wp16, (size_t)DIM * DIM / 4);

    // 1) QKV GEMM (fp16)
    gemm_f16<<<dim3(NQKV/128, MTOT/128), 256, 3 * GSTAGE>>>(
        x16, wq16, bqkv, qkv_p, NQKV, DIM);

    // 2) RMSNorm + RoPE (+1/sqrt(d) into q) + transpose + bf16 hi/lo
    qkv_post<<<BB*LL*HEADS, 128>>>(pe, qscale, kscale);

    // 3) FA2-style flash attention -> g_a16 (fp16)
    flash_attn_v2<<<dim3(LL/128, BH), 256, F2_TOT>>>();

    // 4) proj GEMM (fp16)
    gemm_f16<<<dim3(DIM/128, MTOT/128), 256, 3 * GSTAGE>>>(
        a16, wp16, bproj, out, DIM, DIM);
}